// round 14
// baseline (speedup 1.0000x reference)
#include <cuda_runtime.h>
#include <cuda_fp16.h>
#include <cstdint>

// Problem constants
#define Bb 8
#define Nn 2048
#define Mm 2048
#define Cc 768
#define Hh 12
#define Pp 4
#define Dd 64
#define ROWS (Bb * Nn)
#define GRP  (Bb * Hh)
#define IMG_GRP_ELEMS (Mm * Dd)

// GEMM tiling
#define KC 64
#define NCHUNK (Cc / KC)           // 12
#define STG 2
#define A_STRIDE 144
#define B_STRIDE 272
#define A_TILE (128 * A_STRIDE)    // 18432
#define B_TILE (KC * B_STRIDE)     // 17408
#define STAGEB (A_TILE + B_TILE)   // 35840
#define GEMM_SMEM (1024 + STG * STAGEB)  // 72704

// ---------------- device scratch ----------------
__device__ __half g_qph[ROWS * Cc];
__device__ __half g_imgTh[GRP * IMG_GRP_ELEMS];
__device__ float g_offx[ROWS * Pp];
__device__ float g_logits[GRP * Nn];
__device__ float g_vspart[Bb * 128 * Cc];
__device__ float g_vs[Bb * Cc];
__device__ float g_pv[Bb * Hh * Cc];
__device__ unsigned char g_Ast[2][(ROWS / 128) * NCHUNK * A_TILE];
__device__ unsigned char g_Wst[2][(Cc / 128) * NCHUNK * B_TILE];

// ================= helpers =================
__device__ __forceinline__ uint32_t smem_u32(const void* p) {
    uint32_t a;
    asm("{ .reg .u64 t; cvta.to.shared.u64 t, %1; cvt.u32.u64 %0, t; }"
        : "=r"(a) : "l"(p));
    return a;
}
__device__ __forceinline__ uint32_t f2h2(float x, float y) {
    __half2 t = __floats2half2_rn(x, y);
    return *reinterpret_cast<uint32_t*>(&t);
}
__device__ __forceinline__ void ldm_x4(uint32_t* r, uint32_t addr) {
    asm volatile("ldmatrix.sync.aligned.m8n8.x4.shared.b16 {%0,%1,%2,%3}, [%4];"
                 : "=r"(r[0]), "=r"(r[1]), "=r"(r[2]), "=r"(r[3]) : "r"(addr));
}
__device__ __forceinline__ void ldm_x4t(uint32_t* r, uint32_t addr) {
    asm volatile("ldmatrix.sync.aligned.m8n8.x4.trans.shared.b16 {%0,%1,%2,%3}, [%4];"
                 : "=r"(r[0]), "=r"(r[1]), "=r"(r[2]), "=r"(r[3]) : "r"(addr));
}
__device__ __forceinline__ void mma16816h(uint32_t* c, const uint32_t* a, const uint32_t* b) {
    asm volatile(
        "mma.sync.aligned.m16n8k16.row.col.f16.f16.f16.f16 "
        "{%0,%1}, {%2,%3,%4,%5}, {%6,%7}, {%0,%1};"
        : "+r"(c[0]), "+r"(c[1])
        : "r"(a[0]), "r"(a[1]), "r"(a[2]), "r"(a[3]), "r"(b[0]), "r"(b[1]));
}
__device__ __forceinline__ void bulkcp(uint32_t saddr, const void* g, uint32_t bytes,
                                       uint32_t mbar) {
    asm volatile(
        "cp.async.bulk.shared::cta.global.mbarrier::complete_tx::bytes [%0], [%1], %2, [%3];"
        :: "r"(saddr), "l"(g), "r"(bytes), "r"(mbar) : "memory");
}
#define MBAR_INIT(addr, cnt) \
    asm volatile("mbarrier.init.shared.b64 [%0], %1;" :: "r"(addr), "r"(cnt) : "memory")
#define MBAR_EXPECT_TX(addr, bytes) \
    asm volatile("mbarrier.arrive.expect_tx.shared.b64 _, [%0], %1;" \
                 :: "r"(addr), "r"(bytes) : "memory")
#define MBAR_ARRIVE(addr) \
    asm volatile("mbarrier.arrive.shared.b64 _, [%0];" :: "r"(addr) : "memory")

__device__ __forceinline__ void mbar_wait(uint32_t addr, uint32_t parity) {
    uint32_t done;
    asm volatile(
        "{\n\t.reg .pred p;\n\t"
        "mbarrier.try_wait.parity.acquire.cta.shared::cta.b64 p, [%1], %2;\n\t"
        "selp.b32 %0, 1, 0, p;\n\t}"
        : "=r"(done) : "r"(addr), "r"(parity) : "memory");
    if (!done) {
        asm volatile(
            "{\n\t.reg .pred P1;\n\t"
            "WL_%=:\n\t"
            "mbarrier.try_wait.parity.acquire.cta.shared::cta.b64 P1, [%0], %1, 0x989680;\n\t"
            "@P1 bra.uni WD_%=;\n\t"
            "bra.uni WL_%=;\n\t"
            "WD_%=:\n\t}"
            :: "r"(addr), "r"(parity) : "memory");
    }
}

// ================= staging kernels (fp32 -> fp16 padded tiles) =================
__global__ void __launch_bounds__(256) aconv_kernel(const float* __restrict__ A, int aidx)
{
    const int lid = blockIdx.x * 256 + threadIdx.x;
    const int R = lid / 96;
    const int w = lid % 96;
    const int kc = w >> 3;
    const int cu = w & 7;
    const float4 v0 = *(const float4*)(A + (size_t)R * Cc + kc * 64 + cu * 8);
    const float4 v1 = *(const float4*)(A + (size_t)R * Cc + kc * 64 + cu * 8 + 4);
    uint4 o;
    o.x = f2h2(v0.x, v0.y); o.y = f2h2(v0.z, v0.w);
    o.z = f2h2(v1.x, v1.y); o.w = f2h2(v1.z, v1.w);
    *(uint4*)(g_Ast[aidx] + ((size_t)(R >> 7) * NCHUNK + kc) * A_TILE +
              (R & 127) * A_STRIDE + cu * 16) = o;
}
__global__ void __launch_bounds__(256) wconv2_kernel(const float* __restrict__ Wq,
                                                     const float* __restrict__ Wk)
{
    const int uid = blockIdx.x * 256 + threadIdx.x;
    const int widx = uid >= Cc * 96;
    const int lid = uid - widx * (Cc * 96);
    const float* __restrict__ W = widx ? Wk : Wq;
    const int k = lid / 96;
    const int w = lid % 96;
    const int n0 = w * 8;
    const int cb = n0 >> 7;
    const float4 v0 = *(const float4*)(W + (size_t)k * Cc + n0);
    const float4 v1 = *(const float4*)(W + (size_t)k * Cc + n0 + 4);
    uint4 o;
    o.x = f2h2(v0.x, v0.y); o.y = f2h2(v0.z, v0.w);
    o.z = f2h2(v1.x, v1.y); o.w = f2h2(v1.z, v1.w);
    *(uint4*)(g_Wst[widx] + ((size_t)cb * NCHUNK + (k >> 6)) * B_TILE +
              (k & 63) * B_STRIDE + (n0 & 127) * 2) = o;
}

// ================= GEMM: bulk pipeline + fp16-acc + staged fp16 epilogue ======
__global__ void __launch_bounds__(256, 2) tgemm_kernel(int mode)
{
    extern __shared__ char smem[];
    const uint32_t sb = smem_u32(smem);
    const int tid = threadIdx.x;
    const int lane = tid & 31;
    const int warp = tid >> 5;
    const int wm = warp >> 1;
    const int wn = warp & 1;
    const int blockRow = blockIdx.y * 128;
    const int blockCol = blockIdx.x * 128;

    const unsigned char* __restrict__ Abase =
        g_Ast[mode] + (size_t)blockIdx.y * NCHUNK * A_TILE;
    const unsigned char* __restrict__ Wbase =
        g_Wst[mode] + (size_t)blockIdx.x * NCHUNK * B_TILE;

    const uint32_t FULL = sb;
    const uint32_t EMPTY = sb + 64;
    const uint32_t TILES = sb + 1024;

    if (tid == 0) {
#pragma unroll
        for (int s = 0; s < STG; s++) {
            MBAR_INIT(FULL + 8 * s, 1);
            MBAR_INIT(EMPTY + 8 * s, 8);
        }
    }
    __syncthreads();

    if (tid == 0) {
#pragma unroll
        for (int s = 0; s < STG; s++) {
            MBAR_EXPECT_TX(FULL + 8 * s, STAGEB);
            bulkcp(TILES + s * STAGEB, Abase + (size_t)s * A_TILE, A_TILE, FULL + 8 * s);
            bulkcp(TILES + s * STAGEB + A_TILE, Wbase + (size_t)s * B_TILE, B_TILE,
                   FULL + 8 * s);
        }
    }

    float accf[2][8][4];
    uint32_t acc16[2][8][2];
#pragma unroll
    for (int i = 0; i < 2; i++)
#pragma unroll
        for (int j = 0; j < 8; j++) {
#pragma unroll
            for (int t = 0; t < 4; t++) accf[i][j][t] = 0.0f;
            acc16[i][j][0] = 0u;
            acc16[i][j][1] = 0u;
        }

    int fph[STG] = {0, 0};
    int eph[STG] = {0, 0};

    for (int it = 0; it < NCHUNK; it++) {
        const int s = it % STG;
        mbar_wait(FULL + 8 * s, fph[s]);
        fph[s] ^= 1;

        const uint32_t base = TILES + s * STAGEB;
#pragma unroll
        for (int ks = 0; ks < 4; ks++) {
            uint32_t ah[2][4], bh[4][4];
#pragma unroll
            for (int mt = 0; mt < 2; mt++) {
                const int row = wm * 32 + mt * 16 + (lane & 15);
                ldm_x4(ah[mt], base + row * A_STRIDE + ks * 32 + ((lane >> 4) << 4));
            }
#pragma unroll
            for (int np = 0; np < 4; np++) {
                const int kr = ks * 16 + (lane & 15);
                ldm_x4t(bh[np], base + A_TILE + kr * B_STRIDE + wn * 128 + np * 32 +
                                ((lane >> 4) << 4));
            }
#pragma unroll
            for (int mt = 0; mt < 2; mt++)
#pragma unroll
                for (int j = 0; j < 8; j++)
                    mma16816h(acc16[mt][j], ah[mt], &bh[j >> 1][(j & 1) << 1]);
        }

        if ((it & 1) == 1) {
#pragma unroll
            for (int mt = 0; mt < 2; mt++)
#pragma unroll
                for (int j = 0; j < 8; j++) {
                    const float2 lo =
                        __half22float2(*reinterpret_cast<__half2*>(&acc16[mt][j][0]));
                    const float2 hi =
                        __half22float2(*reinterpret_cast<__half2*>(&acc16[mt][j][1]));
                    accf[mt][j][0] += lo.x;
                    accf[mt][j][1] += lo.y;
                    accf[mt][j][2] += hi.x;
                    accf[mt][j][3] += hi.y;
                    acc16[mt][j][0] = 0u;
                    acc16[mt][j][1] = 0u;
                }
        }

        if (lane == 0) MBAR_ARRIVE(EMPTY + 8 * s);
        if (tid == 0 && it + STG < NCHUNK) {
            mbar_wait(EMPTY + 8 * s, eph[s]);
            eph[s] ^= 1;
            MBAR_EXPECT_TX(FULL + 8 * s, STAGEB);
            bulkcp(base, Abase + (size_t)(it + STG) * A_TILE, A_TILE, FULL + 8 * s);
            bulkcp(base + A_TILE, Wbase + (size_t)(it + STG) * B_TILE, B_TILE,
                   FULL + 8 * s);
        }
    }

    // ---------- staged epilogue ----------
    __syncthreads();
    float* Sf = (float*)(smem + 1024);

    if (mode == 0) {
#pragma unroll
        for (int mt = 0; mt < 2; mt++) {
            const int r0 = wm * 32 + mt * 16 + (lane >> 2);
#pragma unroll
            for (int j = 0; j < 8; j++) {
                const int c0 = wn * 64 + j * 8 + ((lane & 3) << 1);
                *(float2*)(Sf + r0 * 132 + c0) =
                    make_float2(accf[mt][j][0], accf[mt][j][1]);
                *(float2*)(Sf + (r0 + 8) * 132 + c0) =
                    make_float2(accf[mt][j][2], accf[mt][j][3]);
            }
        }
        __syncthreads();
#pragma unroll
        for (int rr = 0; rr < 16; rr++) {
            const int row = warp * 16 + rr;
            const float4 v = *(const float4*)(Sf + row * 132 + lane * 4);
            uint2 h;
            h.x = f2h2(v.x, v.y);
            h.y = f2h2(v.z, v.w);
            *(uint2*)(g_qph + (size_t)(blockRow + row) * Cc + blockCol + lane * 4) = h;
        }
    } else {
#pragma unroll
        for (int mt = 0; mt < 2; mt++) {
#pragma unroll
            for (int j = 0; j < 8; j++) {
#pragma unroll
                for (int e = 0; e < 4; e++) {
                    const int r0 = wm * 32 + mt * 16 + (lane >> 2) + ((e >> 1) << 3);
                    const int dd = j * 8 + ((lane & 3) << 1) + (e & 1);
                    const int x = ((r0 & 31) << 6) + dd;
                    Sf[((wn * 2048 + x) << 2) + (r0 >> 5)] = accf[mt][j][e];
                }
            }
        }
        __syncthreads();
        const int b = blockRow >> 11;
        const int d0 = (blockRow & 2047) >> 5;
        const int h0 = blockCol >> 6;
#pragma unroll
        for (int hb = 0; hb < 2; hb++) {
            __half* dstg = g_imgTh + (size_t)(b * Hh + h0 + hb) * IMG_GRP_ELEMS + d0;
#pragma unroll
            for (int i = 0; i < 8; i++) {
                const int x = i * 256 + tid;
                const float4 v = *(const float4*)(Sf + ((hb * 2048 + x) << 2));
                uint2 h;
                h.x = f2h2(v.x, v.y);
                h.y = f2h2(v.z, v.w);
                *(uint2*)(dstg + (size_t)x * Dd) = h;
            }
        }
    }
}

// ---------------- offsets ----------------
__global__ void __launch_bounds__(256) off_kernel(const float* __restrict__ q,
                                                  const float* __restrict__ offW,
                                                  const float* __restrict__ offb)
{
    const int gwarp = (blockIdx.x * blockDim.x + threadIdx.x) >> 5;
    const int lane = threadIdx.x & 31;
    const float* qrow = q + (size_t)gwarp * Cc;
    float a0 = 0.f, a1 = 0.f, a2 = 0.f, a3 = 0.f;
    for (int c = lane; c < Cc; c += 32) {
        const float qv = qrow[c];
        const float* wr = offW + c * (2 * Pp);
        a0 = fmaf(qv, wr[0], a0);
        a1 = fmaf(qv, wr[2], a1);
        a2 = fmaf(qv, wr[4], a2);
        a3 = fmaf(qv, wr[6], a3);
    }
#pragma unroll
    for (int o = 16; o > 0; o >>= 1) {
        a0 += __shfl_xor_sync(0xffffffffu, a0, o);
        a1 += __shfl_xor_sync(0xffffffffu, a1, o);
        a2 += __shfl_xor_sync(0xffffffffu, a2, o);
        a3 += __shfl_xor_sync(0xffffffffu, a3, o);
    }
    if (lane == 0) {
        g_offx[gwarp * 4 + 0] = a0 + offb[0];
        g_offx[gwarp * 4 + 1] = a1 + offb[2];
        g_offx[gwarp * 4 + 2] = a2 + offb[4];
        g_offx[gwarp * 4 + 3] = a3 + offb[6];
    }
}

// ---------------- v column sums ----------------
__global__ void __launch_bounds__(256) vspart_kernel(const float* __restrict__ v)
{
    const int idx = blockIdx.x * blockDim.x + threadIdx.x;
    const int c4 = idx % (Cc / 4);
    const int chunk = (idx / (Cc / 4)) & 127;
    const int b = idx / ((Cc / 4) * 128);
    const float4* p = (const float4*)(v + ((size_t)b * Mm + (size_t)chunk * 16) * Cc) + c4;
    float4 s = make_float4(0.f, 0.f, 0.f, 0.f);
#pragma unroll
    for (int m = 0; m < 16; m++) {
        float4 t = p[(size_t)m * (Cc / 4)];
        s.x += t.x; s.y += t.y; s.z += t.z; s.w += t.w;
    }
    ((float4*)g_vspart)[idx] = s;
}

__global__ void __launch_bounds__(256) vsred_kernel()
{
    const int idx = blockIdx.x * blockDim.x + threadIdx.x;
    const int c = idx % Cc;
    const int b = idx / Cc;
    float s = 0.f;
#pragma unroll 8
    for (int ch = 0; ch < 128; ch++) s += g_vspart[((size_t)b * 128 + ch) * Cc + c];
    g_vs[idx] = s;
}

// ---------------- pv ----------------
__global__ void __launch_bounds__(256) pv_kernel(const float* __restrict__ vW,
                                                 const float* __restrict__ projW)
{
    __shared__ float vs_s[Cc];
    __shared__ float vsum_s[Cc];
    const int b = blockIdx.x;
    for (int i = threadIdx.x; i < Cc; i += 256) vs_s[i] = g_vs[b * Cc + i];
    __syncthreads();
    for (int o = threadIdx.x; o < Cc; o += 256) {
        float s = 0.f;
        for (int c = 0; c < Cc; c++) s = fmaf(vs_s[c], vW[(size_t)c * Cc + o], s);
        vsum_s[o] = s;
    }
    __syncthreads();
    for (int o = threadIdx.x; o < Hh * Cc; o += 256) {
        const int h = o / Cc;
        const int c = o % Cc;
        float s = 0.f;
#pragma unroll
        for (int d = 0; d < Dd; d++)
            s = fmaf(vsum_s[h * Dd + d], projW[(size_t)(h * Dd + d) * Cc + c], s);
        g_pv[(size_t)b * Hh * Cc + o] = s;
    }
}

// ---------------- sampling + dot (fp16 gathers) ----------------
__global__ void __launch_bounds__(256) sample_kernel()
{
    const int gwarp = (blockIdx.x * blockDim.x + threadIdx.x) >> 5;
    const int lane = threadIdx.x & 31;
    const int g = gwarp >> 11;
    const int n2 = gwarp & 2047;
    const int b = g / Hh;
    const int h = g % Hh;
    const int nq = (h * Nn + n2) / Hh;

    const __half* imgg = g_imgTh + (size_t)g * IMG_GRP_ELEMS;
    float accx = 0.f, accy = 0.f;
#pragma unroll
    for (int p = 0; p < Pp; p++) {
        const float offx = g_offx[((size_t)b * Nn + nq) * Pp + p];
        const float gx = offx / 2047.0f * 2.0f - 1.0f;
        const float x = (gx + 1.0f) * 0.5f * 2047.0f;
        const float x0f = floorf(x);
        const float w = x - x0f;
        const int x0 = (int)x0f;
        const int x1 = x0 + 1;
        const float w0 = (x0 >= 0 && x0 < Mm) ? (1.0f - w) : 0.0f;
        const float w1 = (x1 >= 0 && x1 < Mm) ? w : 0.0f;
        const int x0c = min(max(x0, 0), Mm - 1);
        const int x1c = min(max(x1, 0), Mm - 1);
        const float2 v0 =
            __half22float2(*(const __half2*)(imgg + (size_t)x0c * Dd + 2 * lane));
        const float2 v1 =
            __half22float2(*(const __half2*)(imgg + (size_t)x1c * Dd + 2 * lane));
        accx += w0 * v0.x + w1 * v1.x;
        accy += w0 * v0.y + w1 * v1.y;
    }
    const float2 qv = __half22float2(
        *(const __half2*)(g_qph + ((size_t)b * Nn + n2) * Cc + h * Dd + 2 * lane));
    float partial = accx * qv.x + accy * qv.y;
#pragma unroll
    for (int o = 16; o > 0; o >>= 1) partial += __shfl_xor_sync(0xffffffffu, partial, o);
    if (lane == 0) g_logits[gwarp] = partial * (0.125f * 0.25f);
}

// ---------------- softmax ----------------
__global__ void __launch_bounds__(256) softmax_kernel()
{
    __shared__ float red[256];
    const int row = blockIdx.x;
    float* ptr = g_logits + (size_t)row * Nn;
    const int tid = threadIdx.x;
    float vals[8];
    float m = -1e30f;
#pragma unroll
    for (int i = 0; i < 8; i++) {
        vals[i] = ptr[tid + i * 256];
        m = fmaxf(m, vals[i]);
    }
    red[tid] = m;
    __syncthreads();
    for (int s = 128; s > 0; s >>= 1) {
        if (tid < s) red[tid] = fmaxf(red[tid], red[tid + s]);
        __syncthreads();
    }
    m = red[0];
    __syncthreads();
    float sum = 0.f;
#pragma unroll
    for (int i = 0; i < 8; i++) {
        vals[i] = expf(vals[i] - m);
        sum += vals[i];
    }
    red[tid] = sum;
    __syncthreads();
    for (int s = 128; s > 0; s >>= 1) {
        if (tid < s) red[tid] += red[tid + s];
        __syncthreads();
    }
    const float inv = 1.0f / red[0];
#pragma unroll
    for (int i = 0; i < 8; i++) ptr[tid + i * 256] = vals[i] * inv;
}

// ---------------- output: barrier-free ----------------
__global__ void __launch_bounds__(256) out_kernel(const float* __restrict__ projb,
                                                  float* __restrict__ out)
{
    __shared__ float a_s[32][13];
    const int b = blockIdx.y;
    const int n0 = blockIdx.x * 32;
    const int tid = threadIdx.x;

    for (int i = tid; i < 32 * Hh; i += 256) {
        const int h = i >> 5;
        const int nl = i & 31;
        a_s[nl][h] = g_logits[((size_t)b * Hh + h) * Nn + n0 + nl];
    }
    __syncthreads();

    float pvc[Hh][3];
    float pb[3];
#pragma unroll
    for (int cc = 0; cc < 3; cc++) {
        const int c = tid + cc * 256;
        pb[cc] = projb[c];
#pragma unroll
        for (int h = 0; h < Hh; h++)
            pvc[h][cc] = g_pv[((size_t)b * Hh + h) * Cc + c];
    }

    for (int nl = 0; nl < 32; nl++) {
        float* orow = out + ((size_t)b * Nn + n0 + nl) * Cc + tid;
#pragma unroll
        for (int cc = 0; cc < 3; cc++) {
            float s = pb[cc];
#pragma unroll
            for (int h = 0; h < Hh; h++) s = fmaf(a_s[nl][h], pvc[h][cc], s);
            orow[cc * 256] = s;
        }
    }
}

// ---------------- launch: 3-stream DAG, concurrent GEMMs ----------------
extern "C" void kernel_launch(void* const* d_in, const int* in_sizes, int n_in,
                              void* d_out, int out_size)
{
    (void)in_sizes; (void)n_in; (void)out_size;
    const float* q     = (const float*)d_in[0];
    const float* k     = (const float*)d_in[1];
    const float* v     = (const float*)d_in[2];
    const float* qW    = (const float*)d_in[3];
    const float* kW    = (const float*)d_in[4];
    const float* vW    = (const float*)d_in[5];
    const float* offW  = (const float*)d_in[6];
    const float* offb  = (const float*)d_in[7];
    const float* projW = (const float*)d_in[8];
    const float* projb = (const float*)d_in[9];
    float* out = (float*)d_out;

    static cudaStream_t s_side = nullptr, s_g0 = nullptr;
    static cudaEvent_t e0 = nullptr, e_w = nullptr, e_q = nullptr,
                       e_g0 = nullptr, e1 = nullptr;
    if (s_side == nullptr) {
        cudaStreamCreateWithFlags(&s_side, cudaStreamNonBlocking);
        cudaStreamCreateWithFlags(&s_g0, cudaStreamNonBlocking);
        cudaEventCreateWithFlags(&e0, cudaEventDisableTiming);
        cudaEventCreateWithFlags(&e_w, cudaEventDisableTiming);
        cudaEventCreateWithFlags(&e_q, cudaEventDisableTiming);
        cudaEventCreateWithFlags(&e_g0, cudaEventDisableTiming);
        cudaEventCreateWithFlags(&e1, cudaEventDisableTiming);
        cudaFuncSetAttribute(tgemm_kernel, cudaFuncAttributeMaxDynamicSharedMemorySize,
                             GEMM_SMEM);
    }

    // fork
    cudaEventRecord(e0, 0);
    cudaStreamWaitEvent(s_side, e0, 0);
    cudaStreamWaitEvent(s_g0, e0, 0);

    dim3 ggrid(Cc / 128, ROWS / 128);                               // (6, 128)

    // 1 (main): aconv_k — critical for tgemm1, starts immediately
    aconv_kernel<<<ROWS * 96 / 256, 256>>>(k, 1);
    // 2-4 (side): weights + aconv_q + off
    wconv2_kernel<<<2 * Cc * 96 / 256, 256, 0, s_side>>>(qW, kW);
    cudaEventRecord(e_w, s_side);
    aconv_kernel<<<ROWS * 96 / 256, 256, 0, s_side>>>(q, 0);
    cudaEventRecord(e_q, s_side);                                   // implies e_w too
    off_kernel<<<ROWS / 8, 256, 0, s_side>>>(q, offW, offb);
    // 5 (main): tgemm1 after weights ready
    cudaStreamWaitEvent(0, e_w, 0);
    tgemm_kernel<<<ggrid, 256, GEMM_SMEM>>>(1);
    // 6 (s_g0): tgemm0 concurrent with tgemm1
    cudaStreamWaitEvent(s_g0, e_q, 0);
    tgemm_kernel<<<ggrid, 256, GEMM_SMEM, s_g0>>>(0);
    cudaEventRecord(e_g0, s_g0);
    // side chain continues (independent)
    vspart_kernel<<<(Bb * 128 * (Cc / 4)) / 256, 256, 0, s_side>>>(v);
    vsred_kernel<<<(Bb * Cc) / 256, 256, 0, s_side>>>();
    pv_kernel<<<Bb, 256, 0, s_side>>>(vW, projW);
    cudaEventRecord(e1, s_side);

    // join: sample needs tgemm1 (main), tgemm0 (e_g0), off (within e1 chain)
    cudaStreamWaitEvent(0, e_g0, 0);
    cudaStreamWaitEvent(0, e1, 0);
    sample_kernel<<<(GRP * Nn) / 8, 256>>>();
    softmax_kernel<<<GRP, 256>>>();
    out_kernel<<<dim3(Nn / 32, Bb), 256>>>(projb, out);
}

// round 15
// speedup vs baseline: 1.0576x; 1.0576x over previous
#include <cuda_runtime.h>
#include <cuda_fp16.h>
#include <cstdint>

// Problem constants
#define Bb 8
#define Nn 2048
#define Mm 2048
#define Cc 768
#define Hh 12
#define Pp 4
#define Dd 64
#define ROWS (Bb * Nn)
#define GRP  (Bb * Hh)
#define IMG_GRP_ELEMS (Mm * Dd)

// GEMM tiling
#define KC 64
#define NCHUNK (Cc / KC)           // 12
#define STG 2
#define A_STRIDE 144
#define B_STRIDE 272
#define A_TILE (128 * A_STRIDE)    // 18432
#define B_TILE (KC * B_STRIDE)     // 17408
#define STAGEB (A_TILE + B_TILE)   // 35840
#define GEMM_SMEM (1024 + STG * STAGEB)  // 72704

// ---------------- device scratch ----------------
__device__ __half g_qph[ROWS * Cc];
__device__ __half g_imgTh[GRP * IMG_GRP_ELEMS];
__device__ float g_offx[ROWS * Pp];
__device__ float g_logits[GRP * Nn];
__device__ float g_vspart[Bb * 128 * Cc];
__device__ float g_vs[Bb * Cc];
__device__ float g_pv[Bb * Hh * Cc];
__device__ unsigned char g_Ast[2][(ROWS / 128) * NCHUNK * A_TILE];
__device__ unsigned char g_Wst[2][(Cc / 128) * NCHUNK * B_TILE];

// ================= helpers =================
__device__ __forceinline__ uint32_t smem_u32(const void* p) {
    uint32_t a;
    asm("{ .reg .u64 t; cvta.to.shared.u64 t, %1; cvt.u32.u64 %0, t; }"
        : "=r"(a) : "l"(p));
    return a;
}
__device__ __forceinline__ uint32_t f2h2(float x, float y) {
    __half2 t = __floats2half2_rn(x, y);
    return *reinterpret_cast<uint32_t*>(&t);
}
__device__ __forceinline__ void ldm_x4(uint32_t* r, uint32_t addr) {
    asm volatile("ldmatrix.sync.aligned.m8n8.x4.shared.b16 {%0,%1,%2,%3}, [%4];"
                 : "=r"(r[0]), "=r"(r[1]), "=r"(r[2]), "=r"(r[3]) : "r"(addr));
}
__device__ __forceinline__ void ldm_x4t(uint32_t* r, uint32_t addr) {
    asm volatile("ldmatrix.sync.aligned.m8n8.x4.trans.shared.b16 {%0,%1,%2,%3}, [%4];"
                 : "=r"(r[0]), "=r"(r[1]), "=r"(r[2]), "=r"(r[3]) : "r"(addr));
}
__device__ __forceinline__ void mma16816h(uint32_t* c, const uint32_t* a, const uint32_t* b) {
    asm volatile(
        "mma.sync.aligned.m16n8k16.row.col.f16.f16.f16.f16 "
        "{%0,%1}, {%2,%3,%4,%5}, {%6,%7}, {%0,%1};"
        : "+r"(c[0]), "+r"(c[1])
        : "r"(a[0]), "r"(a[1]), "r"(a[2]), "r"(a[3]), "r"(b[0]), "r"(b[1]));
}
__device__ __forceinline__ void bulkcp(uint32_t saddr, const void* g, uint32_t bytes,
                                       uint32_t mbar) {
    asm volatile(
        "cp.async.bulk.shared::cta.global.mbarrier::complete_tx::bytes [%0], [%1], %2, [%3];"
        :: "r"(saddr), "l"(g), "r"(bytes), "r"(mbar) : "memory");
}
#define MBAR_INIT(addr, cnt) \
    asm volatile("mbarrier.init.shared.b64 [%0], %1;" :: "r"(addr), "r"(cnt) : "memory")
#define MBAR_EXPECT_TX(addr, bytes) \
    asm volatile("mbarrier.arrive.expect_tx.shared.b64 _, [%0], %1;" \
                 :: "r"(addr), "r"(bytes) : "memory")
#define MBAR_ARRIVE(addr) \
    asm volatile("mbarrier.arrive.shared.b64 _, [%0];" :: "r"(addr) : "memory")

__device__ __forceinline__ void mbar_wait(uint32_t addr, uint32_t parity) {
    uint32_t done;
    asm volatile(
        "{\n\t.reg .pred p;\n\t"
        "mbarrier.try_wait.parity.acquire.cta.shared::cta.b64 p, [%1], %2;\n\t"
        "selp.b32 %0, 1, 0, p;\n\t}"
        : "=r"(done) : "r"(addr), "r"(parity) : "memory");
    if (!done) {
        asm volatile(
            "{\n\t.reg .pred P1;\n\t"
            "WL_%=:\n\t"
            "mbarrier.try_wait.parity.acquire.cta.shared::cta.b64 P1, [%0], %1, 0x989680;\n\t"
            "@P1 bra.uni WD_%=;\n\t"
            "bra.uni WL_%=;\n\t"
            "WD_%=:\n\t}"
            :: "r"(addr), "r"(parity) : "memory");
    }
}

// ================= staging kernels (fp32 -> fp16 padded tiles) =================
__global__ void __launch_bounds__(256) aconv_kernel(const float* __restrict__ A, int aidx)
{
    const int lid = blockIdx.x * 256 + threadIdx.x;
    const int R = lid / 96;
    const int w = lid % 96;
    const int kc = w >> 3;
    const int cu = w & 7;
    const float4 v0 = *(const float4*)(A + (size_t)R * Cc + kc * 64 + cu * 8);
    const float4 v1 = *(const float4*)(A + (size_t)R * Cc + kc * 64 + cu * 8 + 4);
    uint4 o;
    o.x = f2h2(v0.x, v0.y); o.y = f2h2(v0.z, v0.w);
    o.z = f2h2(v1.x, v1.y); o.w = f2h2(v1.z, v1.w);
    *(uint4*)(g_Ast[aidx] + ((size_t)(R >> 7) * NCHUNK + kc) * A_TILE +
              (R & 127) * A_STRIDE + cu * 16) = o;
}
__global__ void __launch_bounds__(256) wconv2_kernel(const float* __restrict__ Wq,
                                                     const float* __restrict__ Wk)
{
    const int uid = blockIdx.x * 256 + threadIdx.x;
    const int widx = uid >= Cc * 96;
    const int lid = uid - widx * (Cc * 96);
    const float* __restrict__ W = widx ? Wk : Wq;
    const int k = lid / 96;
    const int w = lid % 96;
    const int n0 = w * 8;
    const int cb = n0 >> 7;
    const float4 v0 = *(const float4*)(W + (size_t)k * Cc + n0);
    const float4 v1 = *(const float4*)(W + (size_t)k * Cc + n0 + 4);
    uint4 o;
    o.x = f2h2(v0.x, v0.y); o.y = f2h2(v0.z, v0.w);
    o.z = f2h2(v1.x, v1.y); o.w = f2h2(v1.z, v1.w);
    *(uint4*)(g_Wst[widx] + ((size_t)cb * NCHUNK + (k >> 6)) * B_TILE +
              (k & 63) * B_STRIDE + (n0 & 127) * 2) = o;
}

// ================= merged GEMM: bulk pipeline + fp16-acc + staged fp16 epilogue ==
__global__ void __launch_bounds__(256, 2) tgemm_kernel()
{
    extern __shared__ char smem[];
    const uint32_t sb = smem_u32(smem);
    const int tid = threadIdx.x;
    const int lane = tid & 31;
    const int warp = tid >> 5;
    const int wm = warp >> 1;
    const int wn = warp & 1;
    const int mode = blockIdx.z;
    const int blockRow = blockIdx.y * 128;
    const int blockCol = blockIdx.x * 128;

    const unsigned char* __restrict__ Abase =
        g_Ast[mode] + (size_t)blockIdx.y * NCHUNK * A_TILE;
    const unsigned char* __restrict__ Wbase =
        g_Wst[mode] + (size_t)blockIdx.x * NCHUNK * B_TILE;

    const uint32_t FULL = sb;
    const uint32_t EMPTY = sb + 64;
    const uint32_t TILES = sb + 1024;

    if (tid == 0) {
#pragma unroll
        for (int s = 0; s < STG; s++) {
            MBAR_INIT(FULL + 8 * s, 1);
            MBAR_INIT(EMPTY + 8 * s, 8);
        }
    }
    __syncthreads();

    if (tid == 0) {
#pragma unroll
        for (int s = 0; s < STG; s++) {
            MBAR_EXPECT_TX(FULL + 8 * s, STAGEB);
            bulkcp(TILES + s * STAGEB, Abase + (size_t)s * A_TILE, A_TILE, FULL + 8 * s);
            bulkcp(TILES + s * STAGEB + A_TILE, Wbase + (size_t)s * B_TILE, B_TILE,
                   FULL + 8 * s);
        }
    }

    float accf[2][8][4];
    uint32_t acc16[2][8][2];
#pragma unroll
    for (int i = 0; i < 2; i++)
#pragma unroll
        for (int j = 0; j < 8; j++) {
#pragma unroll
            for (int t = 0; t < 4; t++) accf[i][j][t] = 0.0f;
            acc16[i][j][0] = 0u;
            acc16[i][j][1] = 0u;
        }

    int fph[STG] = {0, 0};
    int eph[STG] = {0, 0};

    for (int it = 0; it < NCHUNK; it++) {
        const int s = it % STG;
        mbar_wait(FULL + 8 * s, fph[s]);
        fph[s] ^= 1;

        const uint32_t base = TILES + s * STAGEB;
#pragma unroll
        for (int ks = 0; ks < 4; ks++) {
            uint32_t ah[2][4], bh[4][4];
#pragma unroll
            for (int mt = 0; mt < 2; mt++) {
                const int row = wm * 32 + mt * 16 + (lane & 15);
                ldm_x4(ah[mt], base + row * A_STRIDE + ks * 32 + ((lane >> 4) << 4));
            }
#pragma unroll
            for (int np = 0; np < 4; np++) {
                const int kr = ks * 16 + (lane & 15);
                ldm_x4t(bh[np], base + A_TILE + kr * B_STRIDE + wn * 128 + np * 32 +
                                ((lane >> 4) << 4));
            }
#pragma unroll
            for (int mt = 0; mt < 2; mt++)
#pragma unroll
                for (int j = 0; j < 8; j++)
                    mma16816h(acc16[mt][j], ah[mt], &bh[j >> 1][(j & 1) << 1]);
        }

        if ((it & 1) == 1) {
#pragma unroll
            for (int mt = 0; mt < 2; mt++)
#pragma unroll
                for (int j = 0; j < 8; j++) {
                    const float2 lo =
                        __half22float2(*reinterpret_cast<__half2*>(&acc16[mt][j][0]));
                    const float2 hi =
                        __half22float2(*reinterpret_cast<__half2*>(&acc16[mt][j][1]));
                    accf[mt][j][0] += lo.x;
                    accf[mt][j][1] += lo.y;
                    accf[mt][j][2] += hi.x;
                    accf[mt][j][3] += hi.y;
                    acc16[mt][j][0] = 0u;
                    acc16[mt][j][1] = 0u;
                }
        }

        if (lane == 0) MBAR_ARRIVE(EMPTY + 8 * s);
        if (tid == 0 && it + STG < NCHUNK) {
            mbar_wait(EMPTY + 8 * s, eph[s]);
            eph[s] ^= 1;
            MBAR_EXPECT_TX(FULL + 8 * s, STAGEB);
            bulkcp(base, Abase + (size_t)(it + STG) * A_TILE, A_TILE, FULL + 8 * s);
            bulkcp(base + A_TILE, Wbase + (size_t)(it + STG) * B_TILE, B_TILE,
                   FULL + 8 * s);
        }
    }

    // ---------- staged epilogue (fp32 smem staging, fp16 global stores) ----------
    __syncthreads();
    float* Sf = (float*)(smem + 1024);

    if (mode == 0) {
#pragma unroll
        for (int mt = 0; mt < 2; mt++) {
            const int r0 = wm * 32 + mt * 16 + (lane >> 2);
#pragma unroll
            for (int j = 0; j < 8; j++) {
                const int c0 = wn * 64 + j * 8 + ((lane & 3) << 1);
                *(float2*)(Sf + r0 * 132 + c0) =
                    make_float2(accf[mt][j][0], accf[mt][j][1]);
                *(float2*)(Sf + (r0 + 8) * 132 + c0) =
                    make_float2(accf[mt][j][2], accf[mt][j][3]);
            }
        }
        __syncthreads();
#pragma unroll
        for (int rr = 0; rr < 16; rr++) {
            const int row = warp * 16 + rr;
            const float4 v = *(const float4*)(Sf + row * 132 + lane * 4);
            uint2 h;
            h.x = f2h2(v.x, v.y);
            h.y = f2h2(v.z, v.w);
            *(uint2*)(g_qph + (size_t)(blockRow + row) * Cc + blockCol + lane * 4) = h;
        }
    } else {
#pragma unroll
        for (int mt = 0; mt < 2; mt++) {
#pragma unroll
            for (int j = 0; j < 8; j++) {
#pragma unroll
                for (int e = 0; e < 4; e++) {
                    const int r0 = wm * 32 + mt * 16 + (lane >> 2) + ((e >> 1) << 3);
                    const int dd = j * 8 + ((lane & 3) << 1) + (e & 1);
                    const int x = ((r0 & 31) << 6) + dd;
                    Sf[((wn * 2048 + x) << 2) + (r0 >> 5)] = accf[mt][j][e];
                }
            }
        }
        __syncthreads();
        const int b = blockRow >> 11;
        const int d0 = (blockRow & 2047) >> 5;
        const int h0 = blockCol >> 6;
#pragma unroll
        for (int hb = 0; hb < 2; hb++) {
            __half* dstg = g_imgTh + (size_t)(b * Hh + h0 + hb) * IMG_GRP_ELEMS + d0;
#pragma unroll
            for (int i = 0; i < 8; i++) {
                const int x = i * 256 + tid;
                const float4 v = *(const float4*)(Sf + ((hb * 2048 + x) << 2));
                uint2 h;
                h.x = f2h2(v.x, v.y);
                h.y = f2h2(v.z, v.w);
                *(uint2*)(dstg + (size_t)x * Dd) = h;
            }
        }
    }
}

// ---------------- offsets: smem-transposed offW, conflict-free ----------------
__global__ void __launch_bounds__(256) off_kernel(const float* __restrict__ q,
                                                  const float* __restrict__ offW,
                                                  const float* __restrict__ offb)
{
    __shared__ float s[4][Cc];
    const int tid = threadIdx.x;
    for (int i = tid; i < 4 * Cc; i += 256) {
        const int c = i >> 2;
        const int p = i & 3;
        s[p][c] = offW[c * (2 * Pp) + 2 * p];
    }
    __syncthreads();

    const int gwarp = blockIdx.x * 8 + (tid >> 5);
    const int lane = tid & 31;
    const float4* qrow = (const float4*)(q + (size_t)gwarp * Cc);
    float a[4] = {0.f, 0.f, 0.f, 0.f};
#pragma unroll
    for (int i = 0; i < Cc / 128; i++) {           // 6 iterations
        const int c4 = lane + 32 * i;
        const float4 qv = qrow[c4];
        const int c = c4 * 4;
#pragma unroll
        for (int p = 0; p < 4; p++) {
            const float4 wv = *(const float4*)(&s[p][c]);
            a[p] += qv.x * wv.x + qv.y * wv.y + qv.z * wv.z + qv.w * wv.w;
        }
    }
#pragma unroll
    for (int o = 16; o > 0; o >>= 1) {
#pragma unroll
        for (int p = 0; p < 4; p++) a[p] += __shfl_xor_sync(0xffffffffu, a[p], o);
    }
    if (lane < 4) g_offx[gwarp * 4 + lane] = a[lane] + offb[2 * lane];
}

// ---------------- v column sums ----------------
__global__ void __launch_bounds__(256) vspart_kernel(const float* __restrict__ v)
{
    const int idx = blockIdx.x * blockDim.x + threadIdx.x;
    const int c4 = idx % (Cc / 4);
    const int chunk = (idx / (Cc / 4)) & 127;
    const int b = idx / ((Cc / 4) * 128);
    const float4* p = (const float4*)(v + ((size_t)b * Mm + (size_t)chunk * 16) * Cc) + c4;
    float4 s = make_float4(0.f, 0.f, 0.f, 0.f);
#pragma unroll
    for (int m = 0; m < 16; m++) {
        float4 t = p[(size_t)m * (Cc / 4)];
        s.x += t.x; s.y += t.y; s.z += t.z; s.w += t.w;
    }
    ((float4*)g_vspart)[idx] = s;
}

__global__ void __launch_bounds__(256) vsred_kernel()
{
    const int idx = blockIdx.x * blockDim.x + threadIdx.x;
    const int c = idx % Cc;
    const int b = idx / Cc;
    float s = 0.f;
#pragma unroll 8
    for (int ch = 0; ch < 128; ch++) s += g_vspart[((size_t)b * 128 + ch) * Cc + c];
    g_vs[idx] = s;
}

// ---------------- pv ----------------
__global__ void __launch_bounds__(256) pv_kernel(const float* __restrict__ vW,
                                                 const float* __restrict__ projW)
{
    __shared__ float vs_s[Cc];
    __shared__ float vsum_s[Cc];
    const int b = blockIdx.x;
    for (int i = threadIdx.x; i < Cc; i += 256) vs_s[i] = g_vs[b * Cc + i];
    __syncthreads();
    for (int o = threadIdx.x; o < Cc; o += 256) {
        float s = 0.f;
        for (int c = 0; c < Cc; c++) s = fmaf(vs_s[c], vW[(size_t)c * Cc + o], s);
        vsum_s[o] = s;
    }
    __syncthreads();
    for (int o = threadIdx.x; o < Hh * Cc; o += 256) {
        const int h = o / Cc;
        const int c = o % Cc;
        float s = 0.f;
#pragma unroll
        for (int d = 0; d < Dd; d++)
            s = fmaf(vsum_s[h * Dd + d], projW[(size_t)(h * Dd + d) * Cc + c], s);
        g_pv[(size_t)b * Hh * Cc + o] = s;
    }
}

// ---------------- sampling + dot (fp16 gathers) ----------------
__global__ void __launch_bounds__(256) sample_kernel()
{
    const int gwarp = (blockIdx.x * blockDim.x + threadIdx.x) >> 5;
    const int lane = threadIdx.x & 31;
    const int g = gwarp >> 11;
    const int n2 = gwarp & 2047;
    const int b = g / Hh;
    const int h = g % Hh;
    const int nq = (h * Nn + n2) / Hh;

    const __half* imgg = g_imgTh + (size_t)g * IMG_GRP_ELEMS;
    float accx = 0.f, accy = 0.f;
#pragma unroll
    for (int p = 0; p < Pp; p++) {
        const float offx = g_offx[((size_t)b * Nn + nq) * Pp + p];
        const float gx = offx / 2047.0f * 2.0f - 1.0f;
        const float x = (gx + 1.0f) * 0.5f * 2047.0f;
        const float x0f = floorf(x);
        const float w = x - x0f;
        const int x0 = (int)x0f;
        const int x1 = x0 + 1;
        const float w0 = (x0 >= 0 && x0 < Mm) ? (1.0f - w) : 0.0f;
        const float w1 = (x1 >= 0 && x1 < Mm) ? w : 0.0f;
        const int x0c = min(max(x0, 0), Mm - 1);
        const int x1c = min(max(x1, 0), Mm - 1);
        const float2 v0 =
            __half22float2(*(const __half2*)(imgg + (size_t)x0c * Dd + 2 * lane));
        const float2 v1 =
            __half22float2(*(const __half2*)(imgg + (size_t)x1c * Dd + 2 * lane));
        accx += w0 * v0.x + w1 * v1.x;
        accy += w0 * v0.y + w1 * v1.y;
    }
    const float2 qv = __half22float2(
        *(const __half2*)(g_qph + ((size_t)b * Nn + n2) * Cc + h * Dd + 2 * lane));
    float partial = accx * qv.x + accy * qv.y;
#pragma unroll
    for (int o = 16; o > 0; o >>= 1) partial += __shfl_xor_sync(0xffffffffu, partial, o);
    if (lane == 0) g_logits[gwarp] = partial * (0.125f * 0.25f);
}

// ---------------- softmax ----------------
__global__ void __launch_bounds__(256) softmax_kernel()
{
    __shared__ float red[256];
    const int row = blockIdx.x;
    float* ptr = g_logits + (size_t)row * Nn;
    const int tid = threadIdx.x;
    float vals[8];
    float m = -1e30f;
#pragma unroll
    for (int i = 0; i < 8; i++) {
        vals[i] = ptr[tid + i * 256];
        m = fmaxf(m, vals[i]);
    }
    red[tid] = m;
    __syncthreads();
    for (int s = 128; s > 0; s >>= 1) {
        if (tid < s) red[tid] = fmaxf(red[tid], red[tid + s]);
        __syncthreads();
    }
    m = red[0];
    __syncthreads();
    float sum = 0.f;
#pragma unroll
    for (int i = 0; i < 8; i++) {
        vals[i] = expf(vals[i] - m);
        sum += vals[i];
    }
    red[tid] = sum;
    __syncthreads();
    for (int s = 128; s > 0; s >>= 1) {
        if (tid < s) red[tid] += red[tid + s];
        __syncthreads();
    }
    const float inv = 1.0f / red[0];
#pragma unroll
    for (int i = 0; i < 8; i++) ptr[tid + i * 256] = vals[i] * inv;
}

// ---------------- output: barrier-free ----------------
__global__ void __launch_bounds__(256) out_kernel(const float* __restrict__ projb,
                                                  float* __restrict__ out)
{
    __shared__ float a_s[32][13];
    const int b = blockIdx.y;
    const int n0 = blockIdx.x * 32;
    const int tid = threadIdx.x;

    for (int i = tid; i < 32 * Hh; i += 256) {
        const int h = i >> 5;
        const int nl = i & 31;
        a_s[nl][h] = g_logits[((size_t)b * Hh + h) * Nn + n0 + nl];
    }
    __syncthreads();

    float pvc[Hh][3];
    float pb[3];
#pragma unroll
    for (int cc = 0; cc < 3; cc++) {
        const int c = tid + cc * 256;
        pb[cc] = projb[c];
#pragma unroll
        for (int h = 0; h < Hh; h++)
            pvc[h][cc] = g_pv[((size_t)b * Hh + h) * Cc + c];
    }

    for (int nl = 0; nl < 32; nl++) {
        float* orow = out + ((size_t)b * Nn + n0 + nl) * Cc + tid;
#pragma unroll
        for (int cc = 0; cc < 3; cc++) {
            float s = pb[cc];
#pragma unroll
            for (int h = 0; h < Hh; h++) s = fmaf(a_s[nl][h], pvc[h][cc], s);
            orow[cc * 256] = s;
        }
    }
}

// ---------------- launch: R13-style fork/join, merged GEMM ----------------
extern "C" void kernel_launch(void* const* d_in, const int* in_sizes, int n_in,
                              void* d_out, int out_size)
{
    (void)in_sizes; (void)n_in; (void)out_size;
    const float* q     = (const float*)d_in[0];
    const float* k     = (const float*)d_in[1];
    const float* v     = (const float*)d_in[2];
    const float* qW    = (const float*)d_in[3];
    const float* kW    = (const float*)d_in[4];
    const float* vW    = (const float*)d_in[5];
    const float* offW  = (const float*)d_in[6];
    const float* offb  = (const float*)d_in[7];
    const float* projW = (const float*)d_in[8];
    const float* projb = (const float*)d_in[9];
    float* out = (float*)d_out;

    static cudaStream_t s_side = nullptr;
    static cudaEvent_t e0 = nullptr, e_q = nullptr, e1 = nullptr;
    if (s_side == nullptr) {
        cudaStreamCreateWithFlags(&s_side, cudaStreamNonBlocking);
        cudaEventCreateWithFlags(&e0, cudaEventDisableTiming);
        cudaEventCreateWithFlags(&e_q, cudaEventDisableTiming);
        cudaEventCreateWithFlags(&e1, cudaEventDisableTiming);
        cudaFuncSetAttribute(tgemm_kernel, cudaFuncAttributeMaxDynamicSharedMemorySize,
                             GEMM_SMEM);
    }

    // fork
    cudaEventRecord(e0, 0);
    cudaStreamWaitEvent(s_side, e0, 0);

    // main: aconv_k starts immediately; side: weights + aconv_q
    aconv_kernel<<<ROWS * 96 / 256, 256>>>(k, 1);
    wconv2_kernel<<<2 * Cc * 96 / 256, 256, 0, s_side>>>(qW, kW);
    aconv_kernel<<<ROWS * 96 / 256, 256, 0, s_side>>>(q, 0);
    cudaEventRecord(e_q, s_side);          // covers wconv2 + aconv_q (in-order)

    // main: merged GEMM (both modes) once all operands staged
    cudaStreamWaitEvent(0, e_q, 0);
    dim3 ggrid(Cc / 128, ROWS / 128, 2);   // (6, 128, 2)
    tgemm_kernel<<<ggrid, 256, GEMM_SMEM>>>();

    // side chain (independent of GEMM)
    off_kernel<<<ROWS / 8, 256, 0, s_side>>>(q, offW, offb);
    vspart_kernel<<<(Bb * 128 * (Cc / 4)) / 256, 256, 0, s_side>>>(v);
    vsred_kernel<<<(Bb * Cc) / 256, 256, 0, s_side>>>();
    pv_kernel<<<Bb, 256, 0, s_side>>>(vW, projW);
    cudaEventRecord(e1, s_side);

    // join
    cudaStreamWaitEvent(0, e1, 0);
    sample_kernel<<<(GRP * Nn) / 8, 256>>>();
    softmax_kernel<<<GRP, 256>>>();
    out_kernel<<<dim3(Nn / 32, Bb), 256>>>(projb, out);
}

// round 16
// speedup vs baseline: 1.0885x; 1.0292x over previous
#include <cuda_runtime.h>
#include <cuda_fp16.h>
#include <cstdint>

// Problem constants
#define Bb 8
#define Nn 2048
#define Mm 2048
#define Cc 768
#define Hh 12
#define Pp 4
#define Dd 64
#define ROWS (Bb * Nn)
#define GRP  (Bb * Hh)
#define IMG_GRP_ELEMS (Mm * Dd)

// GEMM tiling
#define KC 64
#define NCHUNK (Cc / KC)           // 12
#define STG 2
#define A_STRIDE 144
#define B_STRIDE 272
#define A_TILE (128 * A_STRIDE)    // 18432
#define B_TILE (KC * B_STRIDE)     // 17408
#define STAGEB (A_TILE + B_TILE)   // 35840
#define GEMM_SMEM (1024 + STG * STAGEB)  // 72704

// ---------------- device scratch ----------------
__device__ __half g_qph[ROWS * Cc];
__device__ __half g_imgTh[GRP * IMG_GRP_ELEMS];
__device__ float g_offx[ROWS * Pp];
__device__ float g_logits[GRP * Nn];
__device__ float g_vspart[Bb * 128 * Cc];
__device__ float g_vs[Bb * Cc];
__device__ float g_pv[Bb * Hh * Cc];
__device__ unsigned char g_Ast[2][(ROWS / 128) * NCHUNK * A_TILE];
__device__ unsigned char g_Wst[2][(Cc / 128) * NCHUNK * B_TILE];

// ================= helpers =================
__device__ __forceinline__ uint32_t smem_u32(const void* p) {
    uint32_t a;
    asm("{ .reg .u64 t; cvta.to.shared.u64 t, %1; cvt.u32.u64 %0, t; }"
        : "=r"(a) : "l"(p));
    return a;
}
__device__ __forceinline__ uint32_t f2h2(float x, float y) {
    __half2 t = __floats2half2_rn(x, y);
    return *reinterpret_cast<uint32_t*>(&t);
}
__device__ __forceinline__ void ldm_x4(uint32_t* r, uint32_t addr) {
    asm volatile("ldmatrix.sync.aligned.m8n8.x4.shared.b16 {%0,%1,%2,%3}, [%4];"
                 : "=r"(r[0]), "=r"(r[1]), "=r"(r[2]), "=r"(r[3]) : "r"(addr));
}
__device__ __forceinline__ void ldm_x4t(uint32_t* r, uint32_t addr) {
    asm volatile("ldmatrix.sync.aligned.m8n8.x4.trans.shared.b16 {%0,%1,%2,%3}, [%4];"
                 : "=r"(r[0]), "=r"(r[1]), "=r"(r[2]), "=r"(r[3]) : "r"(addr));
}
__device__ __forceinline__ void mma16816h(uint32_t* c, const uint32_t* a, const uint32_t* b) {
    asm volatile(
        "mma.sync.aligned.m16n8k16.row.col.f16.f16.f16.f16 "
        "{%0,%1}, {%2,%3,%4,%5}, {%6,%7}, {%0,%1};"
        : "+r"(c[0]), "+r"(c[1])
        : "r"(a[0]), "r"(a[1]), "r"(a[2]), "r"(a[3]), "r"(b[0]), "r"(b[1]));
}
__device__ __forceinline__ void bulkcp(uint32_t saddr, const void* g, uint32_t bytes,
                                       uint32_t mbar) {
    asm volatile(
        "cp.async.bulk.shared::cta.global.mbarrier::complete_tx::bytes [%0], [%1], %2, [%3];"
        :: "r"(saddr), "l"(g), "r"(bytes), "r"(mbar) : "memory");
}
#define MBAR_INIT(addr, cnt) \
    asm volatile("mbarrier.init.shared.b64 [%0], %1;" :: "r"(addr), "r"(cnt) : "memory")
#define MBAR_EXPECT_TX(addr, bytes) \
    asm volatile("mbarrier.arrive.expect_tx.shared.b64 _, [%0], %1;" \
                 :: "r"(addr), "r"(bytes) : "memory")
#define MBAR_ARRIVE(addr) \
    asm volatile("mbarrier.arrive.shared.b64 _, [%0];" :: "r"(addr) : "memory")

__device__ __forceinline__ void mbar_wait(uint32_t addr, uint32_t parity) {
    uint32_t done;
    asm volatile(
        "{\n\t.reg .pred p;\n\t"
        "mbarrier.try_wait.parity.acquire.cta.shared::cta.b64 p, [%1], %2;\n\t"
        "selp.b32 %0, 1, 0, p;\n\t}"
        : "=r"(done) : "r"(addr), "r"(parity) : "memory");
    if (!done) {
        asm volatile(
            "{\n\t.reg .pred P1;\n\t"
            "WL_%=:\n\t"
            "mbarrier.try_wait.parity.acquire.cta.shared::cta.b64 P1, [%0], %1, 0x989680;\n\t"
            "@P1 bra.uni WD_%=;\n\t"
            "bra.uni WL_%=;\n\t"
            "WD_%=:\n\t}"
            :: "r"(addr), "r"(parity) : "memory");
    }
}

// ================= staging kernels (fp32 -> fp16 padded tiles) =================
__global__ void __launch_bounds__(256) aconv_kernel(const float* __restrict__ A, int aidx)
{
    const int lid = blockIdx.x * 256 + threadIdx.x;
    const int R = lid / 96;
    const int w = lid % 96;
    const int kc = w >> 3;
    const int cu = w & 7;
    const float4 v0 = *(const float4*)(A + (size_t)R * Cc + kc * 64 + cu * 8);
    const float4 v1 = *(const float4*)(A + (size_t)R * Cc + kc * 64 + cu * 8 + 4);
    uint4 o;
    o.x = f2h2(v0.x, v0.y); o.y = f2h2(v0.z, v0.w);
    o.z = f2h2(v1.x, v1.y); o.w = f2h2(v1.z, v1.w);
    *(uint4*)(g_Ast[aidx] + ((size_t)(R >> 7) * NCHUNK + kc) * A_TILE +
              (R & 127) * A_STRIDE + cu * 16) = o;
}
__global__ void __launch_bounds__(256) wconv2_kernel(const float* __restrict__ Wq,
                                                     const float* __restrict__ Wk)
{
    const int uid = blockIdx.x * 256 + threadIdx.x;
    const int widx = uid >= Cc * 96;
    const int lid = uid - widx * (Cc * 96);
    const float* __restrict__ W = widx ? Wk : Wq;
    const int k = lid / 96;
    const int w = lid % 96;
    const int n0 = w * 8;
    const int cb = n0 >> 7;
    const float4 v0 = *(const float4*)(W + (size_t)k * Cc + n0);
    const float4 v1 = *(const float4*)(W + (size_t)k * Cc + n0 + 4);
    uint4 o;
    o.x = f2h2(v0.x, v0.y); o.y = f2h2(v0.z, v0.w);
    o.z = f2h2(v1.x, v1.y); o.w = f2h2(v1.z, v1.w);
    *(uint4*)(g_Wst[widx] + ((size_t)cb * NCHUNK + (k >> 6)) * B_TILE +
              (k & 63) * B_STRIDE + (n0 & 127) * 2) = o;
}

// ================= merged GEMM: bulk pipeline + fp16-acc + staged fp16 epilogue ==
__global__ void __launch_bounds__(256, 2) tgemm_kernel()
{
    extern __shared__ char smem[];
    const uint32_t sb = smem_u32(smem);
    const int tid = threadIdx.x;
    const int lane = tid & 31;
    const int warp = tid >> 5;
    const int wm = warp >> 1;
    const int wn = warp & 1;
    const int mode = blockIdx.z;
    const int blockRow = blockIdx.y * 128;
    const int blockCol = blockIdx.x * 128;

    const unsigned char* __restrict__ Abase =
        g_Ast[mode] + (size_t)blockIdx.y * NCHUNK * A_TILE;
    const unsigned char* __restrict__ Wbase =
        g_Wst[mode] + (size_t)blockIdx.x * NCHUNK * B_TILE;

    const uint32_t FULL = sb;
    const uint32_t EMPTY = sb + 64;
    const uint32_t TILES = sb + 1024;

    if (tid == 0) {
#pragma unroll
        for (int s = 0; s < STG; s++) {
            MBAR_INIT(FULL + 8 * s, 1);
            MBAR_INIT(EMPTY + 8 * s, 8);
        }
    }
    __syncthreads();

    if (tid == 0) {
#pragma unroll
        for (int s = 0; s < STG; s++) {
            MBAR_EXPECT_TX(FULL + 8 * s, STAGEB);
            bulkcp(TILES + s * STAGEB, Abase + (size_t)s * A_TILE, A_TILE, FULL + 8 * s);
            bulkcp(TILES + s * STAGEB + A_TILE, Wbase + (size_t)s * B_TILE, B_TILE,
                   FULL + 8 * s);
        }
    }

    float accf[2][8][4];
    uint32_t acc16[2][8][2];
#pragma unroll
    for (int i = 0; i < 2; i++)
#pragma unroll
        for (int j = 0; j < 8; j++) {
#pragma unroll
            for (int t = 0; t < 4; t++) accf[i][j][t] = 0.0f;
            acc16[i][j][0] = 0u;
            acc16[i][j][1] = 0u;
        }

    int fph[STG] = {0, 0};
    int eph[STG] = {0, 0};

    for (int it = 0; it < NCHUNK; it++) {
        const int s = it % STG;
        mbar_wait(FULL + 8 * s, fph[s]);
        fph[s] ^= 1;

        const uint32_t base = TILES + s * STAGEB;
#pragma unroll
        for (int ks = 0; ks < 4; ks++) {
            uint32_t ah[2][4], bh[4][4];
#pragma unroll
            for (int mt = 0; mt < 2; mt++) {
                const int row = wm * 32 + mt * 16 + (lane & 15);
                ldm_x4(ah[mt], base + row * A_STRIDE + ks * 32 + ((lane >> 4) << 4));
            }
#pragma unroll
            for (int np = 0; np < 4; np++) {
                const int kr = ks * 16 + (lane & 15);
                ldm_x4t(bh[np], base + A_TILE + kr * B_STRIDE + wn * 128 + np * 32 +
                                ((lane >> 4) << 4));
            }
#pragma unroll
            for (int mt = 0; mt < 2; mt++)
#pragma unroll
                for (int j = 0; j < 8; j++)
                    mma16816h(acc16[mt][j], ah[mt], &bh[j >> 1][(j & 1) << 1]);
        }

        if ((it & 1) == 1) {
#pragma unroll
            for (int mt = 0; mt < 2; mt++)
#pragma unroll
                for (int j = 0; j < 8; j++) {
                    const float2 lo =
                        __half22float2(*reinterpret_cast<__half2*>(&acc16[mt][j][0]));
                    const float2 hi =
                        __half22float2(*reinterpret_cast<__half2*>(&acc16[mt][j][1]));
                    accf[mt][j][0] += lo.x;
                    accf[mt][j][1] += lo.y;
                    accf[mt][j][2] += hi.x;
                    accf[mt][j][3] += hi.y;
                    acc16[mt][j][0] = 0u;
                    acc16[mt][j][1] = 0u;
                }
        }

        if (lane == 0) MBAR_ARRIVE(EMPTY + 8 * s);
        if (tid == 0 && it + STG < NCHUNK) {
            mbar_wait(EMPTY + 8 * s, eph[s]);
            eph[s] ^= 1;
            MBAR_EXPECT_TX(FULL + 8 * s, STAGEB);
            bulkcp(base, Abase + (size_t)(it + STG) * A_TILE, A_TILE, FULL + 8 * s);
            bulkcp(base + A_TILE, Wbase + (size_t)(it + STG) * B_TILE, B_TILE,
                   FULL + 8 * s);
        }
    }

    // ---------- staged epilogue (fp32 smem staging, fp16 global stores) ----------
    __syncthreads();
    float* Sf = (float*)(smem + 1024);

    if (mode == 0) {
#pragma unroll
        for (int mt = 0; mt < 2; mt++) {
            const int r0 = wm * 32 + mt * 16 + (lane >> 2);
#pragma unroll
            for (int j = 0; j < 8; j++) {
                const int c0 = wn * 64 + j * 8 + ((lane & 3) << 1);
                *(float2*)(Sf + r0 * 132 + c0) =
                    make_float2(accf[mt][j][0], accf[mt][j][1]);
                *(float2*)(Sf + (r0 + 8) * 132 + c0) =
                    make_float2(accf[mt][j][2], accf[mt][j][3]);
            }
        }
        __syncthreads();
#pragma unroll
        for (int rr = 0; rr < 16; rr++) {
            const int row = warp * 16 + rr;
            const float4 v = *(const float4*)(Sf + row * 132 + lane * 4);
            uint2 h;
            h.x = f2h2(v.x, v.y);
            h.y = f2h2(v.z, v.w);
            *(uint2*)(g_qph + (size_t)(blockRow + row) * Cc + blockCol + lane * 4) = h;
        }
    } else {
#pragma unroll
        for (int mt = 0; mt < 2; mt++) {
#pragma unroll
            for (int j = 0; j < 8; j++) {
#pragma unroll
                for (int e = 0; e < 4; e++) {
                    const int r0 = wm * 32 + mt * 16 + (lane >> 2) + ((e >> 1) << 3);
                    const int dd = j * 8 + ((lane & 3) << 1) + (e & 1);
                    const int x = ((r0 & 31) << 6) + dd;
                    Sf[((wn * 2048 + x) << 2) + (r0 >> 5)] = accf[mt][j][e];
                }
            }
        }
        __syncthreads();
        const int b = blockRow >> 11;
        const int d0 = (blockRow & 2047) >> 5;
        const int h0 = blockCol >> 6;
#pragma unroll
        for (int hb = 0; hb < 2; hb++) {
            __half* dstg = g_imgTh + (size_t)(b * Hh + h0 + hb) * IMG_GRP_ELEMS + d0;
#pragma unroll
            for (int i = 0; i < 8; i++) {
                const int x = i * 256 + tid;
                const float4 v = *(const float4*)(Sf + ((hb * 2048 + x) << 2));
                uint2 h;
                h.x = f2h2(v.x, v.y);
                h.y = f2h2(v.z, v.w);
                *(uint2*)(dstg + (size_t)x * Dd) = h;
            }
        }
    }
}

// ---------------- offsets: smem-transposed offW, conflict-free ----------------
__global__ void __launch_bounds__(256) off_kernel(const float* __restrict__ q,
                                                  const float* __restrict__ offW,
                                                  const float* __restrict__ offb)
{
    __shared__ float s[4][Cc];
    const int tid = threadIdx.x;
    for (int i = tid; i < 4 * Cc; i += 256) {
        const int c = i >> 2;
        const int p = i & 3;
        s[p][c] = offW[c * (2 * Pp) + 2 * p];
    }
    __syncthreads();

    const int gwarp = blockIdx.x * 8 + (tid >> 5);
    const int lane = tid & 31;
    const float4* qrow = (const float4*)(q + (size_t)gwarp * Cc);
    float a[4] = {0.f, 0.f, 0.f, 0.f};
#pragma unroll
    for (int i = 0; i < Cc / 128; i++) {
        const int c4 = lane + 32 * i;
        const float4 qv = qrow[c4];
        const int c = c4 * 4;
#pragma unroll
        for (int p = 0; p < 4; p++) {
            const float4 wv = *(const float4*)(&s[p][c]);
            a[p] += qv.x * wv.x + qv.y * wv.y + qv.z * wv.z + qv.w * wv.w;
        }
    }
#pragma unroll
    for (int o = 16; o > 0; o >>= 1) {
#pragma unroll
        for (int p = 0; p < 4; p++) a[p] += __shfl_xor_sync(0xffffffffu, a[p], o);
    }
    if (lane < 4) g_offx[gwarp * 4 + lane] = a[lane] + offb[2 * lane];
}

// ---------------- v column sums ----------------
__global__ void __launch_bounds__(256) vspart_kernel(const float* __restrict__ v)
{
    const int idx = blockIdx.x * blockDim.x + threadIdx.x;
    const int c4 = idx % (Cc / 4);
    const int chunk = (idx / (Cc / 4)) & 127;
    const int b = idx / ((Cc / 4) * 128);
    const float4* p = (const float4*)(v + ((size_t)b * Mm + (size_t)chunk * 16) * Cc) + c4;
    float4 s = make_float4(0.f, 0.f, 0.f, 0.f);
#pragma unroll
    for (int m = 0; m < 16; m++) {
        float4 t = p[(size_t)m * (Cc / 4)];
        s.x += t.x; s.y += t.y; s.z += t.z; s.w += t.w;
    }
    ((float4*)g_vspart)[idx] = s;
}

__global__ void __launch_bounds__(256) vsred_kernel()
{
    const int idx = blockIdx.x * blockDim.x + threadIdx.x;
    const int c = idx % Cc;
    const int b = idx / Cc;
    float s = 0.f;
#pragma unroll 8
    for (int ch = 0; ch < 128; ch++) s += g_vspart[((size_t)b * 128 + ch) * Cc + c];
    g_vs[idx] = s;
}

// ---------------- pv ----------------
__global__ void __launch_bounds__(256) pv_kernel(const float* __restrict__ vW,
                                                 const float* __restrict__ projW)
{
    __shared__ float vs_s[Cc];
    __shared__ float vsum_s[Cc];
    const int b = blockIdx.x;
    for (int i = threadIdx.x; i < Cc; i += 256) vs_s[i] = g_vs[b * Cc + i];
    __syncthreads();
    for (int o = threadIdx.x; o < Cc; o += 256) {
        float s = 0.f;
        for (int c = 0; c < Cc; c++) s = fmaf(vs_s[c], vW[(size_t)c * Cc + o], s);
        vsum_s[o] = s;
    }
    __syncthreads();
    for (int o = threadIdx.x; o < Hh * Cc; o += 256) {
        const int h = o / Cc;
        const int c = o % Cc;
        float s = 0.f;
#pragma unroll
        for (int d = 0; d < Dd; d++)
            s = fmaf(vsum_s[h * Dd + d], projW[(size_t)(h * Dd + d) * Cc + c], s);
        g_pv[(size_t)b * Hh * Cc + o] = s;
    }
}

// ---------------- sampling + dot (fp16 gathers) ----------------
__global__ void __launch_bounds__(256) sample_kernel()
{
    const int gwarp = (blockIdx.x * blockDim.x + threadIdx.x) >> 5;
    const int lane = threadIdx.x & 31;
    const int g = gwarp >> 11;
    const int n2 = gwarp & 2047;
    const int b = g / Hh;
    const int h = g % Hh;
    const int nq = (h * Nn + n2) / Hh;

    const __half* imgg = g_imgTh + (size_t)g * IMG_GRP_ELEMS;
    float accx = 0.f, accy = 0.f;
#pragma unroll
    for (int p = 0; p < Pp; p++) {
        const float offx = g_offx[((size_t)b * Nn + nq) * Pp + p];
        const float gx = offx / 2047.0f * 2.0f - 1.0f;
        const float x = (gx + 1.0f) * 0.5f * 2047.0f;
        const float x0f = floorf(x);
        const float w = x - x0f;
        const int x0 = (int)x0f;
        const int x1 = x0 + 1;
        const float w0 = (x0 >= 0 && x0 < Mm) ? (1.0f - w) : 0.0f;
        const float w1 = (x1 >= 0 && x1 < Mm) ? w : 0.0f;
        const int x0c = min(max(x0, 0), Mm - 1);
        const int x1c = min(max(x1, 0), Mm - 1);
        const float2 v0 =
            __half22float2(*(const __half2*)(imgg + (size_t)x0c * Dd + 2 * lane));
        const float2 v1 =
            __half22float2(*(const __half2*)(imgg + (size_t)x1c * Dd + 2 * lane));
        accx += w0 * v0.x + w1 * v1.x;
        accy += w0 * v0.y + w1 * v1.y;
    }
    const float2 qv = __half22float2(
        *(const __half2*)(g_qph + ((size_t)b * Nn + n2) * Cc + h * Dd + 2 * lane));
    float partial = accx * qv.x + accy * qv.y;
#pragma unroll
    for (int o = 16; o > 0; o >>= 1) partial += __shfl_xor_sync(0xffffffffu, partial, o);
    if (lane == 0) g_logits[gwarp] = partial * (0.125f * 0.25f);
}

// ---------------- softmax ----------------
__global__ void __launch_bounds__(256) softmax_kernel()
{
    __shared__ float red[256];
    const int row = blockIdx.x;
    float* ptr = g_logits + (size_t)row * Nn;
    const int tid = threadIdx.x;
    float vals[8];
    float m = -1e30f;
#pragma unroll
    for (int i = 0; i < 8; i++) {
        vals[i] = ptr[tid + i * 256];
        m = fmaxf(m, vals[i]);
    }
    red[tid] = m;
    __syncthreads();
    for (int s = 128; s > 0; s >>= 1) {
        if (tid < s) red[tid] = fmaxf(red[tid], red[tid + s]);
        __syncthreads();
    }
    m = red[0];
    __syncthreads();
    float sum = 0.f;
#pragma unroll
    for (int i = 0; i < 8; i++) {
        vals[i] = expf(vals[i] - m);
        sum += vals[i];
    }
    red[tid] = sum;
    __syncthreads();
    for (int s = 128; s > 0; s >>= 1) {
        if (tid < s) red[tid] += red[tid + s];
        __syncthreads();
    }
    const float inv = 1.0f / red[0];
#pragma unroll
    for (int i = 0; i < 8; i++) ptr[tid + i * 256] = vals[i] * inv;
}

// ---------------- output: barrier-free ----------------
__global__ void __launch_bounds__(256) out_kernel(const float* __restrict__ projb,
                                                  float* __restrict__ out)
{
    __shared__ float a_s[32][13];
    const int b = blockIdx.y;
    const int n0 = blockIdx.x * 32;
    const int tid = threadIdx.x;

    for (int i = tid; i < 32 * Hh; i += 256) {
        const int h = i >> 5;
        const int nl = i & 31;
        a_s[nl][h] = g_logits[((size_t)b * Hh + h) * Nn + n0 + nl];
    }
    __syncthreads();

    float pvc[Hh][3];
    float pb[3];
#pragma unroll
    for (int cc = 0; cc < 3; cc++) {
        const int c = tid + cc * 256;
        pb[cc] = projb[c];
#pragma unroll
        for (int h = 0; h < Hh; h++)
            pvc[h][cc] = g_pv[((size_t)b * Hh + h) * Cc + c];
    }

    for (int nl = 0; nl < 32; nl++) {
        float* orow = out + ((size_t)b * Nn + n0 + nl) * Cc + tid;
#pragma unroll
        for (int cc = 0; cc < 3; cc++) {
            float s = pb[cc];
#pragma unroll
            for (int h = 0; h < Hh; h++) s = fmaf(a_s[nl][h], pvc[h][cc], s);
            orow[cc * 256] = s;
        }
    }
}

// ---------------- launch: side work front-loaded, GEMM runs alone ----------------
extern "C" void kernel_launch(void* const* d_in, const int* in_sizes, int n_in,
                              void* d_out, int out_size)
{
    (void)in_sizes; (void)n_in; (void)out_size;
    const float* q     = (const float*)d_in[0];
    const float* k     = (const float*)d_in[1];
    const float* v     = (const float*)d_in[2];
    const float* qW    = (const float*)d_in[3];
    const float* kW    = (const float*)d_in[4];
    const float* vW    = (const float*)d_in[5];
    const float* offW  = (const float*)d_in[6];
    const float* offb  = (const float*)d_in[7];
    const float* projW = (const float*)d_in[8];
    const float* projb = (const float*)d_in[9];
    float* out = (float*)d_out;

    static cudaStream_t s2 = nullptr, s3 = nullptr;
    static cudaEvent_t e0 = nullptr, e_q = nullptr, e1 = nullptr;
    if (s2 == nullptr) {
        cudaStreamCreateWithFlags(&s2, cudaStreamNonBlocking);
        cudaStreamCreateWithFlags(&s3, cudaStreamNonBlocking);
        cudaEventCreateWithFlags(&e0, cudaEventDisableTiming);
        cudaEventCreateWithFlags(&e_q, cudaEventDisableTiming);
        cudaEventCreateWithFlags(&e1, cudaEventDisableTiming);
        cudaFuncSetAttribute(tgemm_kernel, cudaFuncAttributeMaxDynamicSharedMemorySize,
                             GEMM_SMEM);
    }

    // fork
    cudaEventRecord(e0, 0);
    cudaStreamWaitEvent(s2, e0, 0);
    cudaStreamWaitEvent(s3, e0, 0);

    // main: weights + k staging
    wconv2_kernel<<<2 * Cc * 96 / 256, 256>>>(qW, kW);
    aconv_kernel<<<ROWS * 96 / 256, 256>>>(k, 1);
    // s2: q staging (concurrent with main convs)
    aconv_kernel<<<ROWS * 96 / 256, 256, 0, s2>>>(q, 0);
    cudaEventRecord(e_q, s2);
    // s3: entire side chain at t=0 (depends only on inputs) — drains before GEMM
    off_kernel<<<ROWS / 8, 256, 0, s3>>>(q, offW, offb);
    vspart_kernel<<<(Bb * 128 * (Cc / 4)) / 256, 256, 0, s3>>>(v);
    vsred_kernel<<<(Bb * Cc) / 256, 256, 0, s3>>>();
    pv_kernel<<<Bb, 256, 0, s3>>>(vW, projW);
    cudaEventRecord(e1, s3);

    // main: merged GEMM runs without co-runners
    cudaStreamWaitEvent(0, e_q, 0);
    dim3 ggrid(Cc / 128, ROWS / 128, 2);   // (6, 128, 2)
    tgemm_kernel<<<ggrid, 256, GEMM_SMEM>>>();

    // join + tail
    cudaStreamWaitEvent(0, e1, 0);
    sample_kernel<<<(GRP * Nn) / 8, 256>>>();
    softmax_kernel<<<GRP, 256>>>();
    out_kernel<<<dim3(Nn / 32, Bb), 256>>>(projb, out);
}

// round 17
// speedup vs baseline: 1.1947x; 1.0975x over previous
#include <cuda_runtime.h>
#include <cuda_fp16.h>
#include <cstdint>

// Problem constants
#define Bb 8
#define Nn 2048
#define Mm 2048
#define Cc 768
#define Hh 12
#define Pp 4
#define Dd 64
#define ROWS (Bb * Nn)
#define GRP  (Bb * Hh)
#define IMG_GRP_ELEMS (Mm * Dd)

// GEMM tiling
#define KC 64
#define NCHUNK (Cc / KC)           // 12
#define STG 2
#define A_STRIDE 144
#define B_STRIDE 272
#define A_TILE (128 * A_STRIDE)    // 18432
#define B_TILE (KC * B_STRIDE)     // 17408
#define STAGEB (A_TILE + B_TILE)   // 35840
#define GEMM_SMEM (1024 + STG * STAGEB)  // 72704

// ---------------- device scratch ----------------
__device__ __half g_qph[ROWS * Cc];
__device__ __half g_imgTh[GRP * IMG_GRP_ELEMS];
__device__ float g_offx[ROWS * Pp];
__device__ float g_logits[GRP * Nn];
__device__ float g_vspart[Bb * 128 * Cc];
__device__ float g_vs[Bb * Cc];
__device__ float g_pv[Bb * Hh * Cc];
__device__ unsigned char g_Ast[2][(ROWS / 128) * NCHUNK * A_TILE];
__device__ unsigned char g_Wst[2][(Cc / 128) * NCHUNK * B_TILE];

// ================= helpers =================
__device__ __forceinline__ uint32_t smem_u32(const void* p) {
    uint32_t a;
    asm("{ .reg .u64 t; cvta.to.shared.u64 t, %1; cvt.u32.u64 %0, t; }"
        : "=r"(a) : "l"(p));
    return a;
}
__device__ __forceinline__ uint32_t f2h2(float x, float y) {
    __half2 t = __floats2half2_rn(x, y);
    return *reinterpret_cast<uint32_t*>(&t);
}
__device__ __forceinline__ void ldm_x4(uint32_t* r, uint32_t addr) {
    asm volatile("ldmatrix.sync.aligned.m8n8.x4.shared.b16 {%0,%1,%2,%3}, [%4];"
                 : "=r"(r[0]), "=r"(r[1]), "=r"(r[2]), "=r"(r[3]) : "r"(addr));
}
__device__ __forceinline__ void ldm_x4t(uint32_t* r, uint32_t addr) {
    asm volatile("ldmatrix.sync.aligned.m8n8.x4.trans.shared.b16 {%0,%1,%2,%3}, [%4];"
                 : "=r"(r[0]), "=r"(r[1]), "=r"(r[2]), "=r"(r[3]) : "r"(addr));
}
__device__ __forceinline__ void mma16816h(uint32_t* c, const uint32_t* a, const uint32_t* b) {
    asm volatile(
        "mma.sync.aligned.m16n8k16.row.col.f16.f16.f16.f16 "
        "{%0,%1}, {%2,%3,%4,%5}, {%6,%7}, {%0,%1};"
        : "+r"(c[0]), "+r"(c[1])
        : "r"(a[0]), "r"(a[1]), "r"(a[2]), "r"(a[3]), "r"(b[0]), "r"(b[1]));
}
__device__ __forceinline__ void bulkcp(uint32_t saddr, const void* g, uint32_t bytes,
                                       uint32_t mbar) {
    asm volatile(
        "cp.async.bulk.shared::cta.global.mbarrier::complete_tx::bytes [%0], [%1], %2, [%3];"
        :: "r"(saddr), "l"(g), "r"(bytes), "r"(mbar) : "memory");
}
#define MBAR_INIT(addr, cnt) \
    asm volatile("mbarrier.init.shared.b64 [%0], %1;" :: "r"(addr), "r"(cnt) : "memory")
#define MBAR_EXPECT_TX(addr, bytes) \
    asm volatile("mbarrier.arrive.expect_tx.shared.b64 _, [%0], %1;" \
                 :: "r"(addr), "r"(bytes) : "memory")
#define MBAR_ARRIVE(addr) \
    asm volatile("mbarrier.arrive.shared.b64 _, [%0];" :: "r"(addr) : "memory")

__device__ __forceinline__ void mbar_wait(uint32_t addr, uint32_t parity) {
    uint32_t done;
    asm volatile(
        "{\n\t.reg .pred p;\n\t"
        "mbarrier.try_wait.parity.acquire.cta.shared::cta.b64 p, [%1], %2;\n\t"
        "selp.b32 %0, 1, 0, p;\n\t}"
        : "=r"(done) : "r"(addr), "r"(parity) : "memory");
    if (!done) {
        asm volatile(
            "{\n\t.reg .pred P1;\n\t"
            "WL_%=:\n\t"
            "mbarrier.try_wait.parity.acquire.cta.shared::cta.b64 P1, [%0], %1, 0x989680;\n\t"
            "@P1 bra.uni WD_%=;\n\t"
            "bra.uni WL_%=;\n\t"
            "WD_%=:\n\t}"
            :: "r"(addr), "r"(parity) : "memory");
    }
}

// ================= staging kernels (fp32 -> fp16 padded tiles) =================
__global__ void __launch_bounds__(256) aconv_kernel(const float* __restrict__ A, int aidx)
{
    const int lid = blockIdx.x * 256 + threadIdx.x;
    const int R = lid / 96;
    const int w = lid % 96;
    const int kc = w >> 3;
    const int cu = w & 7;
    const float4 v0 = *(const float4*)(A + (size_t)R * Cc + kc * 64 + cu * 8);
    const float4 v1 = *(const float4*)(A + (size_t)R * Cc + kc * 64 + cu * 8 + 4);
    uint4 o;
    o.x = f2h2(v0.x, v0.y); o.y = f2h2(v0.z, v0.w);
    o.z = f2h2(v1.x, v1.y); o.w = f2h2(v1.z, v1.w);
    *(uint4*)(g_Ast[aidx] + ((size_t)(R >> 7) * NCHUNK + kc) * A_TILE +
              (R & 127) * A_STRIDE + cu * 16) = o;
}
__global__ void __launch_bounds__(256) wconv2_kernel(const float* __restrict__ Wq,
                                                     const float* __restrict__ Wk)
{
    const int uid = blockIdx.x * 256 + threadIdx.x;
    const int widx = uid >= Cc * 96;
    const int lid = uid - widx * (Cc * 96);
    const float* __restrict__ W = widx ? Wk : Wq;
    const int k = lid / 96;
    const int w = lid % 96;
    const int n0 = w * 8;
    const int cb = n0 >> 7;
    const float4 v0 = *(const float4*)(W + (size_t)k * Cc + n0);
    const float4 v1 = *(const float4*)(W + (size_t)k * Cc + n0 + 4);
    uint4 o;
    o.x = f2h2(v0.x, v0.y); o.y = f2h2(v0.z, v0.w);
    o.z = f2h2(v1.x, v1.y); o.w = f2h2(v1.z, v1.w);
    *(uint4*)(g_Wst[widx] + ((size_t)cb * NCHUNK + (k >> 6)) * B_TILE +
              (k & 63) * B_STRIDE + (n0 & 127) * 2) = o;
}

// ================= GEMM: bulk pipeline + fp16-acc + staged fp16 epilogue ======
__global__ void __launch_bounds__(256, 2) tgemm_kernel(int mode)
{
    extern __shared__ char smem[];
    const uint32_t sb = smem_u32(smem);
    const int tid = threadIdx.x;
    const int lane = tid & 31;
    const int warp = tid >> 5;
    const int wm = warp >> 1;
    const int wn = warp & 1;
    const int blockRow = blockIdx.y * 128;
    const int blockCol = blockIdx.x * 128;

    const unsigned char* __restrict__ Abase =
        g_Ast[mode] + (size_t)blockIdx.y * NCHUNK * A_TILE;
    const unsigned char* __restrict__ Wbase =
        g_Wst[mode] + (size_t)blockIdx.x * NCHUNK * B_TILE;

    const uint32_t FULL = sb;
    const uint32_t EMPTY = sb + 64;
    const uint32_t TILES = sb + 1024;

    if (tid == 0) {
#pragma unroll
        for (int s = 0; s < STG; s++) {
            MBAR_INIT(FULL + 8 * s, 1);
            MBAR_INIT(EMPTY + 8 * s, 8);
        }
    }
    __syncthreads();

    if (tid == 0) {
#pragma unroll
        for (int s = 0; s < STG; s++) {
            MBAR_EXPECT_TX(FULL + 8 * s, STAGEB);
            bulkcp(TILES + s * STAGEB, Abase + (size_t)s * A_TILE, A_TILE, FULL + 8 * s);
            bulkcp(TILES + s * STAGEB + A_TILE, Wbase + (size_t)s * B_TILE, B_TILE,
                   FULL + 8 * s);
        }
    }

    float accf[2][8][4];
    uint32_t acc16[2][8][2];
#pragma unroll
    for (int i = 0; i < 2; i++)
#pragma unroll
        for (int j = 0; j < 8; j++) {
#pragma unroll
            for (int t = 0; t < 4; t++) accf[i][j][t] = 0.0f;
            acc16[i][j][0] = 0u;
            acc16[i][j][1] = 0u;
        }

    int fph[STG] = {0, 0};
    int eph[STG] = {0, 0};

    for (int it = 0; it < NCHUNK; it++) {
        const int s = it % STG;
        mbar_wait(FULL + 8 * s, fph[s]);
        fph[s] ^= 1;

        const uint32_t base = TILES + s * STAGEB;
#pragma unroll
        for (int ks = 0; ks < 4; ks++) {
            uint32_t ah[2][4], bh[4][4];
#pragma unroll
            for (int mt = 0; mt < 2; mt++) {
                const int row = wm * 32 + mt * 16 + (lane & 15);
                ldm_x4(ah[mt], base + row * A_STRIDE + ks * 32 + ((lane >> 4) << 4));
            }
#pragma unroll
            for (int np = 0; np < 4; np++) {
                const int kr = ks * 16 + (lane & 15);
                ldm_x4t(bh[np], base + A_TILE + kr * B_STRIDE + wn * 128 + np * 32 +
                                ((lane >> 4) << 4));
            }
#pragma unroll
            for (int mt = 0; mt < 2; mt++)
#pragma unroll
                for (int j = 0; j < 8; j++)
                    mma16816h(acc16[mt][j], ah[mt], &bh[j >> 1][(j & 1) << 1]);
        }

        if ((it & 1) == 1) {
#pragma unroll
            for (int mt = 0; mt < 2; mt++)
#pragma unroll
                for (int j = 0; j < 8; j++) {
                    const float2 lo =
                        __half22float2(*reinterpret_cast<__half2*>(&acc16[mt][j][0]));
                    const float2 hi =
                        __half22float2(*reinterpret_cast<__half2*>(&acc16[mt][j][1]));
                    accf[mt][j][0] += lo.x;
                    accf[mt][j][1] += lo.y;
                    accf[mt][j][2] += hi.x;
                    accf[mt][j][3] += hi.y;
                    acc16[mt][j][0] = 0u;
                    acc16[mt][j][1] = 0u;
                }
        }

        if (lane == 0) MBAR_ARRIVE(EMPTY + 8 * s);
        if (tid == 0 && it + STG < NCHUNK) {
            mbar_wait(EMPTY + 8 * s, eph[s]);
            eph[s] ^= 1;
            MBAR_EXPECT_TX(FULL + 8 * s, STAGEB);
            bulkcp(base, Abase + (size_t)(it + STG) * A_TILE, A_TILE, FULL + 8 * s);
            bulkcp(base + A_TILE, Wbase + (size_t)(it + STG) * B_TILE, B_TILE,
                   FULL + 8 * s);
        }
    }

    // ---------- staged epilogue (fp32 smem staging, fp16 global stores) ----------
    __syncthreads();
    float* Sf = (float*)(smem + 1024);

    if (mode == 0) {
#pragma unroll
        for (int mt = 0; mt < 2; mt++) {
            const int r0 = wm * 32 + mt * 16 + (lane >> 2);
#pragma unroll
            for (int j = 0; j < 8; j++) {
                const int c0 = wn * 64 + j * 8 + ((lane & 3) << 1);
                *(float2*)(Sf + r0 * 132 + c0) =
                    make_float2(accf[mt][j][0], accf[mt][j][1]);
                *(float2*)(Sf + (r0 + 8) * 132 + c0) =
                    make_float2(accf[mt][j][2], accf[mt][j][3]);
            }
        }
        __syncthreads();
#pragma unroll
        for (int rr = 0; rr < 16; rr++) {
            const int row = warp * 16 + rr;
            const float4 v = *(const float4*)(Sf + row * 132 + lane * 4);
            uint2 h;
            h.x = f2h2(v.x, v.y);
            h.y = f2h2(v.z, v.w);
            *(uint2*)(g_qph + (size_t)(blockRow + row) * Cc + blockCol + lane * 4) = h;
        }
    } else {
#pragma unroll
        for (int mt = 0; mt < 2; mt++) {
#pragma unroll
            for (int j = 0; j < 8; j++) {
#pragma unroll
                for (int e = 0; e < 4; e++) {
                    const int r0 = wm * 32 + mt * 16 + (lane >> 2) + ((e >> 1) << 3);
                    const int dd = j * 8 + ((lane & 3) << 1) + (e & 1);
                    const int x = ((r0 & 31) << 6) + dd;
                    Sf[((wn * 2048 + x) << 2) + (r0 >> 5)] = accf[mt][j][e];
                }
            }
        }
        __syncthreads();
        const int b = blockRow >> 11;
        const int d0 = (blockRow & 2047) >> 5;
        const int h0 = blockCol >> 6;
#pragma unroll
        for (int hb = 0; hb < 2; hb++) {
            __half* dstg = g_imgTh + (size_t)(b * Hh + h0 + hb) * IMG_GRP_ELEMS + d0;
#pragma unroll
            for (int i = 0; i < 8; i++) {
                const int x = i * 256 + tid;
                const float4 v = *(const float4*)(Sf + ((hb * 2048 + x) << 2));
                uint2 h;
                h.x = f2h2(v.x, v.y);
                h.y = f2h2(v.z, v.w);
                *(uint2*)(dstg + (size_t)x * Dd) = h;
            }
        }
    }
}

// ---------------- offsets: smem-transposed offW, conflict-free ----------------
__global__ void __launch_bounds__(256) off_kernel(const float* __restrict__ q,
                                                  const float* __restrict__ offW,
                                                  const float* __restrict__ offb)
{
    __shared__ float s[4][Cc];
    const int tid = threadIdx.x;
    for (int i = tid; i < 4 * Cc; i += 256) {
        const int c = i >> 2;
        const int p = i & 3;
        s[p][c] = offW[c * (2 * Pp) + 2 * p];
    }
    __syncthreads();

    const int gwarp = blockIdx.x * 8 + (tid >> 5);
    const int lane = tid & 31;
    const float4* qrow = (const float4*)(q + (size_t)gwarp * Cc);
    float a[4] = {0.f, 0.f, 0.f, 0.f};
#pragma unroll
    for (int i = 0; i < Cc / 128; i++) {
        const int c4 = lane + 32 * i;
        const float4 qv = qrow[c4];
        const int c = c4 * 4;
#pragma unroll
        for (int p = 0; p < 4; p++) {
            const float4 wv = *(const float4*)(&s[p][c]);
            a[p] += qv.x * wv.x + qv.y * wv.y + qv.z * wv.z + qv.w * wv.w;
        }
    }
#pragma unroll
    for (int o = 16; o > 0; o >>= 1) {
#pragma unroll
        for (int p = 0; p < 4; p++) a[p] += __shfl_xor_sync(0xffffffffu, a[p], o);
    }
    if (lane < 4) g_offx[gwarp * 4 + lane] = a[lane] + offb[2 * lane];
}

// ---------------- v column sums ----------------
__global__ void __launch_bounds__(256) vspart_kernel(const float* __restrict__ v)
{
    const int idx = blockIdx.x * blockDim.x + threadIdx.x;
    const int c4 = idx % (Cc / 4);
    const int chunk = (idx / (Cc / 4)) & 127;
    const int b = idx / ((Cc / 4) * 128);
    const float4* p = (const float4*)(v + ((size_t)b * Mm + (size_t)chunk * 16) * Cc) + c4;
    float4 s = make_float4(0.f, 0.f, 0.f, 0.f);
#pragma unroll
    for (int m = 0; m < 16; m++) {
        float4 t = p[(size_t)m * (Cc / 4)];
        s.x += t.x; s.y += t.y; s.z += t.z; s.w += t.w;
    }
    ((float4*)g_vspart)[idx] = s;
}

__global__ void __launch_bounds__(256) vsred_kernel()
{
    const int idx = blockIdx.x * blockDim.x + threadIdx.x;
    const int c = idx % Cc;
    const int b = idx / Cc;
    float s = 0.f;
#pragma unroll 8
    for (int ch = 0; ch < 128; ch++) s += g_vspart[((size_t)b * 128 + ch) * Cc + c];
    g_vs[idx] = s;
}

// ---------------- pv ----------------
__global__ void __launch_bounds__(256) pv_kernel(const float* __restrict__ vW,
                                                 const float* __restrict__ projW)
{
    __shared__ float vs_s[Cc];
    __shared__ float vsum_s[Cc];
    const int b = blockIdx.x;
    for (int i = threadIdx.x; i < Cc; i += 256) vs_s[i] = g_vs[b * Cc + i];
    __syncthreads();
    for (int o = threadIdx.x; o < Cc; o += 256) {
        float s = 0.f;
        for (int c = 0; c < Cc; c++) s = fmaf(vs_s[c], vW[(size_t)c * Cc + o], s);
        vsum_s[o] = s;
    }
    __syncthreads();
    for (int o = threadIdx.x; o < Hh * Cc; o += 256) {
        const int h = o / Cc;
        const int c = o % Cc;
        float s = 0.f;
#pragma unroll
        for (int d = 0; d < Dd; d++)
            s = fmaf(vsum_s[h * Dd + d], projW[(size_t)(h * Dd + d) * Cc + c], s);
        g_pv[(size_t)b * Hh * Cc + o] = s;
    }
}

// ---------------- sampling + dot (fp16 gathers) ----------------
__global__ void __launch_bounds__(256) sample_kernel()
{
    const int gwarp = (blockIdx.x * blockDim.x + threadIdx.x) >> 5;
    const int lane = threadIdx.x & 31;
    const int g = gwarp >> 11;
    const int n2 = gwarp & 2047;
    const int b = g / Hh;
    const int h = g % Hh;
    const int nq = (h * Nn + n2) / Hh;

    const __half* imgg = g_imgTh + (size_t)g * IMG_GRP_ELEMS;
    float accx = 0.f, accy = 0.f;
#pragma unroll
    for (int p = 0; p < Pp; p++) {
        const float offx = g_offx[((size_t)b * Nn + nq) * Pp + p];
        const float gx = offx / 2047.0f * 2.0f - 1.0f;
        const float x = (gx + 1.0f) * 0.5f * 2047.0f;
        const float x0f = floorf(x);
        const float w = x - x0f;
        const int x0 = (int)x0f;
        const int x1 = x0 + 1;
        const float w0 = (x0 >= 0 && x0 < Mm) ? (1.0f - w) : 0.0f;
        const float w1 = (x1 >= 0 && x1 < Mm) ? w : 0.0f;
        const int x0c = min(max(x0, 0), Mm - 1);
        const int x1c = min(max(x1, 0), Mm - 1);
        const float2 v0 =
            __half22float2(*(const __half2*)(imgg + (size_t)x0c * Dd + 2 * lane));
        const float2 v1 =
            __half22float2(*(const __half2*)(imgg + (size_t)x1c * Dd + 2 * lane));
        accx += w0 * v0.x + w1 * v1.x;
        accy += w0 * v0.y + w1 * v1.y;
    }
    const float2 qv = __half22float2(
        *(const __half2*)(g_qph + ((size_t)b * Nn + n2) * Cc + h * Dd + 2 * lane));
    float partial = accx * qv.x + accy * qv.y;
#pragma unroll
    for (int o = 16; o > 0; o >>= 1) partial += __shfl_xor_sync(0xffffffffu, partial, o);
    if (lane == 0) g_logits[gwarp] = partial * (0.125f * 0.25f);
}

// ---------------- softmax ----------------
__global__ void __launch_bounds__(256) softmax_kernel()
{
    __shared__ float red[256];
    const int row = blockIdx.x;
    float* ptr = g_logits + (size_t)row * Nn;
    const int tid = threadIdx.x;
    float vals[8];
    float m = -1e30f;
#pragma unroll
    for (int i = 0; i < 8; i++) {
        vals[i] = ptr[tid + i * 256];
        m = fmaxf(m, vals[i]);
    }
    red[tid] = m;
    __syncthreads();
    for (int s = 128; s > 0; s >>= 1) {
        if (tid < s) red[tid] = fmaxf(red[tid], red[tid + s]);
        __syncthreads();
    }
    m = red[0];
    __syncthreads();
    float sum = 0.f;
#pragma unroll
    for (int i = 0; i < 8; i++) {
        vals[i] = expf(vals[i] - m);
        sum += vals[i];
    }
    red[tid] = sum;
    __syncthreads();
    for (int s = 128; s > 0; s >>= 1) {
        if (tid < s) red[tid] += red[tid + s];
        __syncthreads();
    }
    const float inv = 1.0f / red[0];
#pragma unroll
    for (int i = 0; i < 8; i++) ptr[tid + i * 256] = vals[i] * inv;
}

// ---------------- output: barrier-free ----------------
__global__ void __launch_bounds__(256) out_kernel(const float* __restrict__ projb,
                                                  float* __restrict__ out)
{
    __shared__ float a_s[32][13];
    const int b = blockIdx.y;
    const int n0 = blockIdx.x * 32;
    const int tid = threadIdx.x;

    for (int i = tid; i < 32 * Hh; i += 256) {
        const int h = i >> 5;
        const int nl = i & 31;
        a_s[nl][h] = g_logits[((size_t)b * Hh + h) * Nn + n0 + nl];
    }
    __syncthreads();

    float pvc[Hh][3];
    float pb[3];
#pragma unroll
    for (int cc = 0; cc < 3; cc++) {
        const int c = tid + cc * 256;
        pb[cc] = projb[c];
#pragma unroll
        for (int h = 0; h < Hh; h++)
            pvc[h][cc] = g_pv[((size_t)b * Hh + h) * Cc + c];
    }

    for (int nl = 0; nl < 32; nl++) {
        float* orow = out + ((size_t)b * Nn + n0 + nl) * Cc + tid;
#pragma unroll
        for (int cc = 0; cc < 3; cc++) {
            float s = pb[cc];
#pragma unroll
            for (int h = 0; h < Hh; h++) s = fmaf(a_s[nl][h], pvc[h][cc], s);
            orow[cc * 256] = s;
        }
    }
}

// ---------------- launch: exact R13 schedule ----------------
extern "C" void kernel_launch(void* const* d_in, const int* in_sizes, int n_in,
                              void* d_out, int out_size)
{
    (void)in_sizes; (void)n_in; (void)out_size;
    const float* q     = (const float*)d_in[0];
    const float* k     = (const float*)d_in[1];
    const float* v     = (const float*)d_in[2];
    const float* qW    = (const float*)d_in[3];
    const float* kW    = (const float*)d_in[4];
    const float* vW    = (const float*)d_in[5];
    const float* offW  = (const float*)d_in[6];
    const float* offb  = (const float*)d_in[7];
    const float* projW = (const float*)d_in[8];
    const float* projb = (const float*)d_in[9];
    float* out = (float*)d_out;

    static cudaStream_t s_side = nullptr;
    static cudaEvent_t s_e0 = nullptr, s_e1 = nullptr, s_e2 = nullptr;
    if (s_side == nullptr) {
        cudaStreamCreateWithFlags(&s_side, cudaStreamNonBlocking);
        cudaEventCreateWithFlags(&s_e0, cudaEventDisableTiming);
        cudaEventCreateWithFlags(&s_e1, cudaEventDisableTiming);
        cudaEventCreateWithFlags(&s_e2, cudaEventDisableTiming);
        cudaFuncSetAttribute(tgemm_kernel, cudaFuncAttributeMaxDynamicSharedMemorySize,
                             GEMM_SMEM);
    }

    // fork
    cudaEventRecord(s_e0, 0);
    cudaStreamWaitEvent(s_side, s_e0, 0);

    dim3 ggrid(Cc / 128, ROWS / 128);                               // (6, 128)
    wconv2_kernel<<<2 * Cc * 96 / 256, 256>>>(qW, kW);              // 1 (main)
    aconv_kernel<<<ROWS * 96 / 256, 256>>>(k, 1);                   // 2 (main)
    aconv_kernel<<<ROWS * 96 / 256, 256, 0, s_side>>>(q, 0);        // 3 (side)
    cudaEventRecord(s_e2, s_side);
    tgemm_kernel<<<ggrid, 256, GEMM_SMEM>>>(1);                     // 4 (main, profiled)
    cudaStreamWaitEvent(0, s_e2, 0);
    tgemm_kernel<<<ggrid, 256, GEMM_SMEM>>>(0);                     // 5 (main)

    // side chain (independent of GEMMs)
    off_kernel<<<ROWS / 8, 256, 0, s_side>>>(q, offW, offb);
    vspart_kernel<<<(Bb * 128 * (Cc / 4)) / 256, 256, 0, s_side>>>(v);
    vsred_kernel<<<(Bb * Cc) / 256, 256, 0, s_side>>>();
    pv_kernel<<<Bb, 256, 0, s_side>>>(vW, projW);
    cudaEventRecord(s_e1, s_side);

    // join
    cudaStreamWaitEvent(0, s_e1, 0);
    sample_kernel<<<(GRP * Nn) / 8, 256>>>();
    softmax_kernel<<<GRP, 256>>>();
    out_kernel<<<dim3(Nn / 32, Bb), 256>>>(projb, out);
}